// round 2
// baseline (speedup 1.0000x reference)
#include <cuda_runtime.h>
#include <math.h>

// Problem constants
#define NROWS   115200          // 6*64*300
#define CDIM    256
#define THDIM   157             // 144 + 10 + 3
#define NPOSE_  144

// Scratch (device globals: allocation-free per harness rules)
__device__ float g_xw1[(size_t)NROWS * CDIM];     // x @ W1[:256] + b1 (iteration-invariant)
__device__ float g_h1 [(size_t)NROWS * CDIM];
__device__ float g_h2 [(size_t)NROWS * CDIM];
__device__ float g_theta[(size_t)NROWS * THDIM];

// ---------------------------------------------------------------------------
// theta <- broadcast(concat(init_contrep, init_shape, init_cam))
// ---------------------------------------------------------------------------
__global__ void init_theta_kernel(const float* __restrict__ cr,
                                  const float* __restrict__ sh,
                                  const float* __restrict__ cam)
{
    int i = blockIdx.x * blockDim.x + threadIdx.x;
    if (i >= NROWS * THDIM) return;
    int j = i % THDIM;
    float v;
    if (j < NPOSE_)            v = cr[j];
    else if (j < NPOSE_ + 10)  v = sh[j - NPOSE_];
    else                       v = cam[j - NPOSE_ - 10];
    g_theta[i] = v;
}

// ---------------------------------------------------------------------------
// Tiled fp32 GEMM:  C = epilogue(A[M,K] @ B[K,N])
// MODE 0: C = acc + bias[n]
// MODE 1: C = relu(acc + res[row,n])          (bias unused; b1 folded into res)
// MODE 2: C = acc + bias[n] + res[row,n]      (theta update; res==C aliasing OK,
//                                              each element written exactly once)
// BM=BN=128, BK=8, 256 threads, 8x8 microtile. M must be multiple of 128 (115200 ok).
// ---------------------------------------------------------------------------
template<int MODE>
__global__ void __launch_bounds__(256)
gemm_kernel(const float* __restrict__ A, const float* __restrict__ B,
            const float* __restrict__ bias, const float* __restrict__ res,
            float* __restrict__ C, int M, int N, int K)
{
    __shared__ float sA[8][128];   // [k][m]
    __shared__ float sB[8][128];   // [k][n]

    const int tid = threadIdx.x;
    const int tx  = tid & 15;      // 0..15 -> n microtile
    const int ty  = tid >> 4;      // 0..15 -> m microtile
    const int bm  = blockIdx.y * 128;
    const int bn  = blockIdx.x * 128;

    float acc[8][8];
#pragma unroll
    for (int i = 0; i < 8; i++)
#pragma unroll
        for (int j = 0; j < 8; j++) acc[i][j] = 0.f;

    for (int k0 = 0; k0 < K; k0 += 8) {
        // Load A tile (128 rows x 8 k), store transposed sA[k][m].
#pragma unroll
        for (int i = 0; i < 4; i++) {
            int li = tid + i * 256;          // 0..1023
            int ar = li >> 3;                // row in tile
            int ac = li & 7;                 // k in tile
            int gk = k0 + ac;
            float v = 0.f;
            if (gk < K) v = A[(size_t)(bm + ar) * K + gk];
            sA[ac][ar] = v;
        }
        // Load B tile (8 k x 128 cols), coalesced.
#pragma unroll
        for (int i = 0; i < 4; i++) {
            int li = tid + i * 256;
            int br = li >> 7;                // k in tile
            int bc = li & 127;               // col in tile
            int gk = k0 + br;
            int gn = bn + bc;
            float v = 0.f;
            if (gk < K && gn < N) v = B[(size_t)gk * N + gn];
            sB[br][bc] = v;
        }
        __syncthreads();

#pragma unroll
        for (int k = 0; k < 8; k++) {
            float ra[8], rb[8];
#pragma unroll
            for (int i = 0; i < 8; i++) ra[i] = sA[k][ty * 8 + i];
#pragma unroll
            for (int j = 0; j < 8; j++) rb[j] = sB[k][tx * 8 + j];
#pragma unroll
            for (int i = 0; i < 8; i++)
#pragma unroll
                for (int j = 0; j < 8; j++)
                    acc[i][j] = fmaf(ra[i], rb[j], acc[i][j]);
        }
        __syncthreads();
    }

    // Epilogue
#pragma unroll
    for (int i = 0; i < 8; i++) {
        int row = bm + ty * 8 + i;
#pragma unroll
        for (int j = 0; j < 8; j++) {
            int col = bn + tx * 8 + j;
            if (col < N) {
                size_t o = (size_t)row * N + col;
                float v = acc[i][j];
                if (MODE == 0) {
                    v += bias[col];
                } else if (MODE == 1) {
                    v += res[o];
                    v = fmaxf(v, 0.f);
                } else {
                    v += bias[col] + res[o];
                }
                C[o] = v;
            }
        }
    }
}

// ---------------------------------------------------------------------------
// rot6d -> rotmat. One thread per (row, joint): n*24 threads.
// pose layout per joint: [v0..v5] reshaped (3,2): a1=(v0,v2,v4), a2=(v1,v3,v5)
// output stack((b1,b2,b3), axis=-1): row-major 3x3 with COLUMNS b1,b2,b3.
// ---------------------------------------------------------------------------
__global__ void rot6d_kernel(float* __restrict__ out)
{
    int idx = blockIdx.x * blockDim.x + threadIdx.x;
    if (idx >= NROWS * 24) return;
    int row = idx / 24;
    int j   = idx % 24;
    const float* p = g_theta + (size_t)row * THDIM + j * 6;
    float a1x = p[0], a2x = p[1];
    float a1y = p[2], a2y = p[3];
    float a1z = p[4], a2z = p[5];

    float n1 = sqrtf(a1x * a1x + a1y * a1y + a1z * a1z);
    n1 = fmaxf(n1, 1e-12f);
    float b1x = a1x / n1, b1y = a1y / n1, b1z = a1z / n1;

    float d = b1x * a2x + b1y * a2y + b1z * a2z;
    float u2x = a2x - d * b1x, u2y = a2y - d * b1y, u2z = a2z - d * b1z;
    float n2 = sqrtf(u2x * u2x + u2y * u2y + u2z * u2z);
    n2 = fmaxf(n2, 1e-12f);
    float b2x = u2x / n2, b2y = u2y / n2, b2z = u2z / n2;

    float b3x = b1y * b2z - b1z * b2y;
    float b3y = b1z * b2x - b1x * b2z;
    float b3z = b1x * b2y - b1y * b2x;

    float* o = out + (size_t)idx * 9;
    o[0] = b1x; o[1] = b2x; o[2] = b3x;
    o[3] = b1y; o[4] = b2y; o[5] = b3y;
    o[6] = b1z; o[7] = b2z; o[8] = b3z;
}

// betas (n,10) then camera (n,3), appended after rotmat block.
__global__ void copy_bc_kernel(float* __restrict__ out)
{
    int i = blockIdx.x * blockDim.x + threadIdx.x;
    if (i >= NROWS * 13) return;
    int row = i / 13;
    int k   = i % 13;
    float v = g_theta[(size_t)row * THDIM + NPOSE_ + k];
    size_t OB = (size_t)NROWS * 216;           // end of rotmat block
    if (k < 10) out[OB + (size_t)row * 10 + k] = v;
    else        out[OB + (size_t)NROWS * 10 + (size_t)row * 3 + (k - 10)] = v;
}

// ---------------------------------------------------------------------------
extern "C" void kernel_launch(void* const* d_in, const int* in_sizes, int n_in,
                              void* d_out, int out_size)
{
    const float* x   = (const float*)d_in[0];
    // d_in[1] = pred_class (unused by reference outputs)
    const float* W1  = (const float*)d_in[2];   // (413, 256) row-major
    const float* b1  = (const float*)d_in[3];
    const float* W2  = (const float*)d_in[4];   // (256, 256)
    const float* b2  = (const float*)d_in[5];
    const float* W3  = (const float*)d_in[6];   // (256, 157)
    const float* b3  = (const float*)d_in[7];
    const float* cr  = (const float*)d_in[8];   // init_contrep (144)
    const float* sh  = (const float*)d_in[9];   // init_shape   (10)
    const float* cam = (const float*)d_in[10];  // init_cam     (3)
    float* out = (float*)d_out;

    float *p_xw1, *p_h1, *p_h2, *p_theta;
    cudaGetSymbolAddress((void**)&p_xw1,   g_xw1);
    cudaGetSymbolAddress((void**)&p_h1,    g_h1);
    cudaGetSymbolAddress((void**)&p_h2,    g_h2);
    cudaGetSymbolAddress((void**)&p_theta, g_theta);

    const int MB = NROWS / 128;                 // 900

    init_theta_kernel<<<(NROWS * THDIM + 255) / 256, 256>>>(cr, sh, cam);

    // xw1 = x @ W1[:256] + b1   (iteration-invariant, hoisted)
    gemm_kernel<0><<<dim3(2, MB), 256>>>(x, W1, b1, nullptr, p_xw1,
                                         NROWS, CDIM, CDIM);

    const float* W1t = W1 + (size_t)CDIM * CDIM;  // rows 256..412 of W1

    for (int it = 0; it < 3; it++) {
        // h1 = relu(xw1 + theta @ W1t)
        gemm_kernel<1><<<dim3(2, MB), 256>>>(p_theta, W1t, nullptr, p_xw1, p_h1,
                                             NROWS, CDIM, THDIM);
        // h2 = h1 @ W2 + b2
        gemm_kernel<0><<<dim3(2, MB), 256>>>(p_h1, W2, b2, nullptr, p_h2,
                                             NROWS, CDIM, CDIM);
        // theta += h2 @ W3 + b3
        gemm_kernel<2><<<dim3(2, MB), 256>>>(p_h2, W3, b3, p_theta, p_theta,
                                             NROWS, THDIM, CDIM);
    }

    rot6d_kernel<<<(NROWS * 24 + 255) / 256, 256>>>(out);
    copy_bc_kernel<<<(NROWS * 13 + 255) / 256, 256>>>(out);
}

// round 3
// speedup vs baseline: 2.2475x; 2.2475x over previous
#include <cuda_runtime.h>
#include <math.h>

#define NROWS  115200           // 6*64*300
#define CDIM   256
#define THDIM  157              // 144 + 10 + 3
#define THPAD  160              // theta row stride (float4-aligned, pads zero)
#define NPOSE_ 144

// Scratch (device globals: allocation-free per harness rules)
__device__ float g_xw1  [(size_t)NROWS * CDIM];   // x @ W1[:256] + b1 (invariant)
__device__ float g_h    [(size_t)NROWS * CDIM];   // hidden activations (iters 2,3)
__device__ float g_theta[(size_t)NROWS * THPAD];  // theta, padded stride
__device__ float g_w23  [CDIM * THPAD];           // W2 @ W3, padded cols
__device__ float g_cvec [CDIM];                   // theta0 @ W1t
__device__ float g_bvec2[THPAD];                  // b2 @ W3 + b3
__device__ float g_tbias[THPAD];                  // theta0 + bvec2

// ---------------------------------------------------------------------------
// Precompute W23[k][n] = sum_j W2[k][j] * W3[j][n]  (pads zeroed)
// ---------------------------------------------------------------------------
__global__ void prep_w23(const float* __restrict__ W2, const float* __restrict__ W3)
{
    int k = blockIdx.x;         // 0..255
    int n = threadIdx.x;        // 0..159
    float acc = 0.f;
    if (n < THDIM) {
        for (int j = 0; j < CDIM; j++)
            acc = fmaf(W2[k * CDIM + j], W3[j * THDIM + n], acc);
    }
    g_w23[k * THPAD + n] = (n < THDIM) ? acc : 0.f;
}

// ---------------------------------------------------------------------------
// Precompute cvec, bvec2, tbias from inits + weights. One block, 256 threads.
// ---------------------------------------------------------------------------
__global__ void prep_vecs(const float* __restrict__ W1,
                          const float* __restrict__ b2,
                          const float* __restrict__ W3,
                          const float* __restrict__ b3,
                          const float* __restrict__ cr,
                          const float* __restrict__ sh,
                          const float* __restrict__ cam)
{
    __shared__ float th0[THDIM];
    int t = threadIdx.x;
    if (t < THDIM) {
        float v;
        if (t < NPOSE_)            v = cr[t];
        else if (t < NPOSE_ + 10)  v = sh[t - NPOSE_];
        else                       v = cam[t - NPOSE_ - 10];
        th0[t] = v;
    }
    __syncthreads();
    // cvec[k] = sum_t th0[t] * W1[(256+t)*256 + k]
    {
        float acc = 0.f;
        for (int j = 0; j < THDIM; j++)
            acc = fmaf(th0[j], W1[(size_t)(CDIM + j) * CDIM + t], acc);
        g_cvec[t] = acc;
    }
    if (t < THPAD) {
        float bv = 0.f;
        if (t < THDIM) {
            for (int j = 0; j < CDIM; j++)
                bv = fmaf(b2[j], W3[j * THDIM + t], bv);
            bv += b3[t];
        }
        g_bvec2[t] = bv;
        g_tbias[t] = bv + ((t < THDIM) ? th0[t] : 0.f);
    }
}

// ---------------------------------------------------------------------------
// Double-buffered tiled fp32 GEMM. BM=128, BK=16, BN in {128, 64}. 256 thr.
// MODE 0: C = acc + bias[n]
// MODE 1: C = relu(acc + res[row,n])
// MODE 2: C = acc + bias[n] + res[row,n]   (res==C aliasing safe: RAW per-thread)
// AOP  1: A-element op: a = relu(a + cvec[k])  (fused iter-1 hidden layer)
// Pads (col in [N, Npad)) are written as 0.
// Requirements: M % 128 == 0; lda % 4 == 0; A rows padded so k in
// [0, 16*ceil(K/16)) is in-bounds (true for K=256 exact, K=157 w/ lda=160).
// ---------------------------------------------------------------------------
template<int AOP>
__device__ __forceinline__ void ldA(const float* __restrict__ A, int lda, int bm,
                                    int k0, const float* __restrict__ cvec,
                                    int tid, float4* aReg)
{
#pragma unroll
    for (int i = 0; i < 2; i++) {
        int idx = tid + i * 256;
        int row = idx >> 2;
        int gk  = k0 + (idx & 3) * 4;
        float4 v = *reinterpret_cast<const float4*>(A + (size_t)(bm + row) * lda + gk);
        if (AOP == 1) {
            v.x = fmaxf(v.x + cvec[gk + 0], 0.f);
            v.y = fmaxf(v.y + cvec[gk + 1], 0.f);
            v.z = fmaxf(v.z + cvec[gk + 2], 0.f);
            v.w = fmaxf(v.w + cvec[gk + 3], 0.f);
        }
        aReg[i] = v;
    }
}

template<int BN>
__device__ __forceinline__ void ldB(const float* __restrict__ B, int ldb, int Nb,
                                    int bn, int k0, int K, int tid, float4* bReg)
{
    constexpr int NB4 = BN / 4;
    constexpr int NL  = (16 * NB4) / 256;
#pragma unroll
    for (int i = 0; i < NL; i++) {
        int idx = tid + i * 256;
        int gk  = k0 + idx / NB4;
        int gn  = bn + (idx % NB4) * 4;
        float4 v = make_float4(0.f, 0.f, 0.f, 0.f);
        if (gk < K && gn < Nb)
            v = *reinterpret_cast<const float4*>(B + (size_t)gk * ldb + gn);
        bReg[i] = v;
    }
}

template<int MODE, int AOP, int BN>
__global__ void __launch_bounds__(256, 2)
gemm_db(const float* __restrict__ A, int lda,
        const float* __restrict__ B, int ldb, int Nb,
        const float* __restrict__ bias,
        const float* __restrict__ res, int ldres,
        const float* __restrict__ cvec,
        float* __restrict__ C, int ldc,
        int M, int N, int Npad, int K)
{
    constexpr int TN  = BN / 16;            // cols per thread: 8 or 4
    constexpr int NB4 = BN / 4;
    constexpr int NL  = (16 * NB4) / 256;

    __shared__ float sA[2][16][132];        // [k][m], padded vs STS conflicts
    __shared__ float sB[2][16][BN];         // [k][n]

    const int tid = threadIdx.x;
    const int tx  = tid & 15;
    const int ty  = tid >> 4;
    const int bm  = blockIdx.y * 128;
    const int bn  = blockIdx.x * BN;

    float4 aReg[2], bReg[NL];
    float  acc[8][TN];
#pragma unroll
    for (int i = 0; i < 8; i++)
#pragma unroll
        for (int j = 0; j < TN; j++) acc[i][j] = 0.f;

    const int ntiles = (K + 15) >> 4;

    // Prologue: tile 0 -> buf 0
    ldA<AOP>(A, lda, bm, 0, cvec, tid, aReg);
    ldB<BN>(B, ldb, Nb, bn, 0, K, tid, bReg);
#pragma unroll
    for (int i = 0; i < 2; i++) {
        int idx = tid + i * 256;
        int row = idx >> 2, c4 = (idx & 3) * 4;
        sA[0][c4 + 0][row] = aReg[i].x;
        sA[0][c4 + 1][row] = aReg[i].y;
        sA[0][c4 + 2][row] = aReg[i].z;
        sA[0][c4 + 3][row] = aReg[i].w;
    }
#pragma unroll
    for (int i = 0; i < NL; i++) {
        int idx = tid + i * 256;
        *reinterpret_cast<float4*>(&sB[0][idx / NB4][(idx % NB4) * 4]) = bReg[i];
    }
    __syncthreads();

    for (int t = 0; t < ntiles; t++) {
        const int cur = t & 1;
        if (t + 1 < ntiles) {
            ldA<AOP>(A, lda, bm, (t + 1) * 16, cvec, tid, aReg);
            ldB<BN>(B, ldb, Nb, bn, (t + 1) * 16, K, tid, bReg);
        }
#pragma unroll
        for (int k = 0; k < 16; k++) {
            float ra[8], rb[TN];
#pragma unroll
            for (int i = 0; i < 8; i++)  ra[i] = sA[cur][k][ty * 8 + i];
#pragma unroll
            for (int j = 0; j < TN; j++) rb[j] = sB[cur][k][tx * TN + j];
#pragma unroll
            for (int i = 0; i < 8; i++)
#pragma unroll
                for (int j = 0; j < TN; j++)
                    acc[i][j] = fmaf(ra[i], rb[j], acc[i][j]);
        }
        if (t + 1 < ntiles) {
            const int nxt = cur ^ 1;
#pragma unroll
            for (int i = 0; i < 2; i++) {
                int idx = tid + i * 256;
                int row = idx >> 2, c4 = (idx & 3) * 4;
                sA[nxt][c4 + 0][row] = aReg[i].x;
                sA[nxt][c4 + 1][row] = aReg[i].y;
                sA[nxt][c4 + 2][row] = aReg[i].z;
                sA[nxt][c4 + 3][row] = aReg[i].w;
            }
#pragma unroll
            for (int i = 0; i < NL; i++) {
                int idx = tid + i * 256;
                *reinterpret_cast<float4*>(&sB[nxt][idx / NB4][(idx % NB4) * 4]) = bReg[i];
            }
            __syncthreads();
        }
    }

    // Epilogue
#pragma unroll
    for (int i = 0; i < 8; i++) {
        int row = bm + ty * 8 + i;
#pragma unroll
        for (int j = 0; j < TN; j++) {
            int col = bn + tx * TN + j;
            if (col < Npad) {
                float v = 0.f;
                if (col < N) {
                    v = acc[i][j];
                    if (MODE == 0) {
                        v += bias[col];
                    } else if (MODE == 1) {
                        v += res[(size_t)row * ldres + col];
                        v = fmaxf(v, 0.f);
                    } else {
                        v += bias[col] + res[(size_t)row * ldres + col];
                    }
                }
                C[(size_t)row * ldc + col] = v;
            }
        }
    }
}

// ---------------------------------------------------------------------------
// rot6d -> rotmat. One thread per (row, joint).
// ---------------------------------------------------------------------------
__global__ void rot6d_kernel(float* __restrict__ out)
{
    int idx = blockIdx.x * blockDim.x + threadIdx.x;
    if (idx >= NROWS * 24) return;
    int row = idx / 24;
    int j   = idx % 24;
    const float* p = g_theta + (size_t)row * THPAD + j * 6;
    float a1x = p[0], a2x = p[1];
    float a1y = p[2], a2y = p[3];
    float a1z = p[4], a2z = p[5];

    float n1 = sqrtf(a1x * a1x + a1y * a1y + a1z * a1z);
    n1 = fmaxf(n1, 1e-12f);
    float b1x = a1x / n1, b1y = a1y / n1, b1z = a1z / n1;

    float d = b1x * a2x + b1y * a2y + b1z * a2z;
    float u2x = a2x - d * b1x, u2y = a2y - d * b1y, u2z = a2z - d * b1z;
    float n2 = sqrtf(u2x * u2x + u2y * u2y + u2z * u2z);
    n2 = fmaxf(n2, 1e-12f);
    float b2x = u2x / n2, b2y = u2y / n2, b2z = u2z / n2;

    float b3x = b1y * b2z - b1z * b2y;
    float b3y = b1z * b2x - b1x * b2z;
    float b3z = b1x * b2y - b1y * b2x;

    float* o = out + (size_t)idx * 9;
    o[0] = b1x; o[1] = b2x; o[2] = b3x;
    o[3] = b1y; o[4] = b2y; o[5] = b3y;
    o[6] = b1z; o[7] = b2z; o[8] = b3z;
}

__global__ void copy_bc_kernel(float* __restrict__ out)
{
    int i = blockIdx.x * blockDim.x + threadIdx.x;
    if (i >= NROWS * 13) return;
    int row = i / 13;
    int k   = i % 13;
    float v = g_theta[(size_t)row * THPAD + NPOSE_ + k];
    size_t OB = (size_t)NROWS * 216;
    if (k < 10) out[OB + (size_t)row * 10 + k] = v;
    else        out[OB + (size_t)NROWS * 10 + (size_t)row * 3 + (k - 10)] = v;
}

// ---------------------------------------------------------------------------
extern "C" void kernel_launch(void* const* d_in, const int* in_sizes, int n_in,
                              void* d_out, int out_size)
{
    const float* x   = (const float*)d_in[0];
    // d_in[1] = pred_class (unused)
    const float* W1  = (const float*)d_in[2];   // (413, 256)
    const float* b1  = (const float*)d_in[3];
    const float* W2  = (const float*)d_in[4];   // (256, 256)
    const float* b2  = (const float*)d_in[5];
    const float* W3  = (const float*)d_in[6];   // (256, 157)
    const float* b3  = (const float*)d_in[7];
    const float* cr  = (const float*)d_in[8];
    const float* sh  = (const float*)d_in[9];
    const float* cam = (const float*)d_in[10];
    float* out = (float*)d_out;

    float *p_xw1, *p_h, *p_theta, *p_w23, *p_cvec, *p_bvec2, *p_tbias;
    cudaGetSymbolAddress((void**)&p_xw1,   g_xw1);
    cudaGetSymbolAddress((void**)&p_h,     g_h);
    cudaGetSymbolAddress((void**)&p_theta, g_theta);
    cudaGetSymbolAddress((void**)&p_w23,   g_w23);
    cudaGetSymbolAddress((void**)&p_cvec,  g_cvec);
    cudaGetSymbolAddress((void**)&p_bvec2, g_bvec2);
    cudaGetSymbolAddress((void**)&p_tbias, g_tbias);

    const float* W1t = W1 + (size_t)CDIM * CDIM;   // rows 256..412
    const int MB = NROWS / 128;                    // 900

    prep_w23<<<CDIM, THPAD>>>(W2, W3);
    prep_vecs<<<1, CDIM>>>(W1, b2, W3, b3, cr, sh, cam);

    // xw1 = x @ W1[:256] + b1
    gemm_db<0, 0, 128><<<dim3(2, MB), 256>>>(
        x, CDIM, W1, CDIM, CDIM, b1, nullptr, 0, nullptr,
        p_xw1, CDIM, NROWS, CDIM, CDIM, CDIM);

    // Iter 1 (fused): theta = relu(xw1 + cvec) @ W23 + (theta0 + bvec2)
    gemm_db<0, 1, 64><<<dim3(3, MB), 256>>>(
        p_xw1, CDIM, p_w23, THPAD, THPAD, p_tbias, nullptr, 0, p_cvec,
        p_theta, THPAD, NROWS, THDIM, THPAD, CDIM);

    for (int it = 0; it < 2; it++) {
        // h = relu(xw1 + theta @ W1t)
        gemm_db<1, 0, 128><<<dim3(2, MB), 256>>>(
            p_theta, THPAD, W1t, CDIM, CDIM, nullptr, p_xw1, CDIM, nullptr,
            p_h, CDIM, NROWS, CDIM, CDIM, THDIM);
        // theta += h @ W23 + bvec2
        gemm_db<2, 0, 64><<<dim3(3, MB), 256>>>(
            p_h, CDIM, p_w23, THPAD, THPAD, p_bvec2, p_theta, THPAD, nullptr,
            p_theta, THPAD, NROWS, THDIM, THPAD, CDIM);
    }

    rot6d_kernel<<<(NROWS * 24 + 255) / 256, 256>>>(out);
    copy_bc_kernel<<<(NROWS * 13 + 255) / 256, 256>>>(out);
}

// round 6
// speedup vs baseline: 5.2161x; 2.3209x over previous
#include <cuda_runtime.h>
#include <cuda_bf16.h>
#include <math.h>
#include <stdint.h>

#define NROWS  115200           // 6*64*300
#define CDIM   256
#define THDIM  157
#define THPAD  160
#define NPOSE_ 144

// ---------------- scratch (device globals; no allocation) ----------------
__device__ __align__(16) float g_xw1  [(size_t)NROWS * CDIM];
__device__ __align__(16) float g_h    [(size_t)NROWS * CDIM];
__device__ __align__(16) float g_theta[(size_t)NROWS * THPAD];
__device__ __align__(16) float g_w23f [CDIM * THPAD];
__device__ __align__(16) float g_cvec [CDIM];
__device__ __align__(16) float g_bvec2[THPAD];
__device__ __align__(16) float g_tbias[THPAD];

// Pre-split, pre-swizzled bf16 weights, layout [chunk64][n][128B row, XOR-swizzled]
__device__ __align__(16) __nv_bfloat16 g_w1a_hi[4 * 256 * 64], g_w1a_lo[4 * 256 * 64];
__device__ __align__(16) __nv_bfloat16 g_w23_hi[4 * 160 * 64], g_w23_lo[4 * 160 * 64];
__device__ __align__(16) __nv_bfloat16 g_w1t_hi[3 * 256 * 64], g_w1t_lo[3 * 256 * 64];

// ---------------- helpers (baseline PTX only: sm_80-class) ----------------
static __device__ __forceinline__ uint32_t smem_u32(const void* p) {
    uint32_t a;
    asm("{ .reg .u64 t; cvta.to.shared.u64 t, %1; cvt.u32.u64 %0, t; }"
        : "=r"(a) : "l"(p));
    return a;
}
static __device__ __forceinline__ void ldsm_x4(uint32_t* r, uint32_t a) {
    asm volatile("ldmatrix.sync.aligned.m8n8.x4.shared.b16 {%0,%1,%2,%3}, [%4];"
        : "=r"(r[0]), "=r"(r[1]), "=r"(r[2]), "=r"(r[3]) : "r"(a));
}
static __device__ __forceinline__ void ldsm_x2(uint32_t* r, uint32_t a) {
    asm volatile("ldmatrix.sync.aligned.m8n8.x2.shared.b16 {%0,%1}, [%2];"
        : "=r"(r[0]), "=r"(r[1]) : "r"(a));
}
static __device__ __forceinline__ void mma_bf16(float* d, const uint32_t* a,
                                                const uint32_t* b) {
    asm volatile(
        "mma.sync.aligned.m16n8k16.row.col.f32.bf16.bf16.f32 "
        "{%0,%1,%2,%3}, {%4,%5,%6,%7}, {%8,%9}, {%0,%1,%2,%3};"
        : "+f"(d[0]), "+f"(d[1]), "+f"(d[2]), "+f"(d[3])
        : "r"(a[0]), "r"(a[1]), "r"(a[2]), "r"(a[3]), "r"(b[0]), "r"(b[1]));
}
#define CP_ASYNC16(sa, gp) \
    asm volatile("cp.async.cg.shared.global [%0], [%1], 16;" :: "r"(sa), "l"(gp))
#define CP_COMMIT() asm volatile("cp.async.commit_group;" ::: "memory")
#define CP_WAIT0()  asm volatile("cp.async.wait_group 0;" ::: "memory")

// XOR swizzle: byte offset within a 128B row; row parity XORed into bits 4..6.
__device__ __forceinline__ uint32_t swz(int row, int colbyte) {
    return (uint32_t)(row * 128 + (colbyte ^ ((row & 7) << 4)));
}

// ---------------- weight / vector prep ----------------
__global__ void prep_w23(const float* __restrict__ W2, const float* __restrict__ W3)
{
    int k = blockIdx.x;          // 0..255
    int n = threadIdx.x;         // 0..159
    float acc = 0.f;
    if (n < THDIM)
        for (int j = 0; j < CDIM; j++)
            acc = fmaf(W2[k * CDIM + j], W3[j * THDIM + n], acc);
    g_w23f[k * THPAD + n] = (n < THDIM) ? acc : 0.f;
}

__global__ void prep_vecs(const float* __restrict__ W1, const float* __restrict__ b2,
                          const float* __restrict__ W3, const float* __restrict__ b3,
                          const float* __restrict__ cr, const float* __restrict__ sh,
                          const float* __restrict__ cam)
{
    __shared__ float th0[THDIM];
    int t = threadIdx.x;
    if (t < THDIM) {
        float v;
        if (t < NPOSE_)           v = cr[t];
        else if (t < NPOSE_ + 10) v = sh[t - NPOSE_];
        else                      v = cam[t - NPOSE_ - 10];
        th0[t] = v;
    }
    __syncthreads();
    {
        float acc = 0.f;
        for (int j = 0; j < THDIM; j++)
            acc = fmaf(th0[j], W1[(size_t)(CDIM + j) * CDIM + t], acc);
        g_cvec[t] = acc;
    }
    if (t < THPAD) {
        float bv = 0.f;
        if (t < THDIM) {
            for (int j = 0; j < CDIM; j++)
                bv = fmaf(b2[j], W3[j * THDIM + t], bv);
            bv += b3[t];
        }
        g_bvec2[t] = bv;
        g_tbias[t] = bv + ((t < THDIM) ? th0[t] : 0.f);
    }
}

static __device__ __forceinline__ void put_w(__nv_bfloat16* hiArr, __nv_bfloat16* loArr,
                                             int Nrows, int k, int n, float v)
{
    unsigned short hb = __bfloat16_as_ushort(__float2bfloat16_rn(v));
    float vh = __bfloat162float(__ushort_as_bfloat16(hb));
    unsigned short lb = __bfloat16_as_ushort(__float2bfloat16_rn(v - vh));
    int chunk = k >> 6, kc = k & 63;
    size_t byte = (size_t)chunk * ((size_t)Nrows * 128) + swz(n, kc * 2);
    *(unsigned short*)((char*)hiArr + byte) = hb;
    *(unsigned short*)((char*)loArr + byte) = lb;
}

__global__ void conv_w1a(const float* __restrict__ W1)
{
    int idx = blockIdx.x * blockDim.x + threadIdx.x;
    if (idx >= 256 * 256) return;
    int k = idx >> 8, n = idx & 255;
    put_w(g_w1a_hi, g_w1a_lo, 256, k, n, W1[(size_t)k * CDIM + n]);
}
__global__ void conv_w23k(void)
{
    int idx = blockIdx.x * blockDim.x + threadIdx.x;
    if (idx >= 256 * 160) return;
    int k = idx / 160, n = idx % 160;
    put_w(g_w23_hi, g_w23_lo, 160, k, n, g_w23f[k * THPAD + n]);
}
__global__ void conv_w1t(const float* __restrict__ W1)
{
    int idx = blockIdx.x * blockDim.x + threadIdx.x;
    if (idx >= 192 * 256) return;
    int k = idx >> 8, n = idx & 255;
    float v = (k < THDIM) ? W1[(size_t)(CDIM + k) * CDIM + n] : 0.f;
    put_w(g_w1t_hi, g_w1t_lo, 256, k, n, v);
}

// ---------------- tensor-core GEMM via mma.sync (HMMA) ----------------
// C[128-tile, BN] = epilogue( A @ Bt ).  3xBF16 split, fp32 accum in regs.
// 8 warps = 2(m) x 4(n); warp tile 64 x (BN/4); m16n8k16 fragments.
// MODE 0: +bias[n];  1: relu(+res);  2: +bias[n]+res.   AOP 1: a=relu(a+cvec[k]).
template<int BN, int MODE, int AOP>
__global__ void __launch_bounds__(256, 1)
mma_gemm(const float* __restrict__ A, int lda, int Kreal, int Kpad,
         const __nv_bfloat16* __restrict__ Bhi, const __nv_bfloat16* __restrict__ Blo,
         int Ntot,
         const float* __restrict__ bias, const float* __restrict__ res, int ldres,
         const float* __restrict__ cvec, float* __restrict__ C, int ldc)
{
    constexpr int MF = 4;          // m-frags per warp (4 x 16 = 64 rows)
    constexpr int NF = BN / 32;    // n-frags per warp (NF x 8 cols)
    constexpr int ABYTES = 128 * 128;     // 128 rows x 64 k x bf16, one split
    constexpr int BBYTES = BN * 128;      // BN rows x 64 k x bf16, one split

    extern __shared__ char smem[];
    const uint32_t sbase = smem_u32(smem);
    const int tid  = threadIdx.x;
    const int lane = tid & 31;
    const int wid  = tid >> 5;
    const int wm   = wid & 1;      // 0..1
    const int wn   = wid >> 1;     // 0..3
    const int bm   = blockIdx.y * 128;
    const int bn   = blockIdx.x * BN;

    // smem: A splits [buf*2+sp]*ABYTES ; B splits at 4*ABYTES + [buf*2+sp]*BBYTES
    const uint32_t aoff0 = 0, boff0 = 4 * ABYTES;

    float acc[MF][NF][4];
#pragma unroll
    for (int i = 0; i < MF; i++)
#pragma unroll
        for (int j = 0; j < NF; j++)
#pragma unroll
            for (int q = 0; q < 4; q++) acc[i][j][q] = 0.f;

    const int nch = Kpad >> 6;

    // ---- A: global fp32 -> regs (with optional AOP) ----
    auto loadA_g = [&](int chunk, float4* aR) {
        int k0 = chunk << 6;
#pragma unroll
        for (int i = 0; i < 8; i++) {
            int idx = tid + i * 256;          // 0..2047
            int row = idx >> 4;               // 0..127
            int gk  = k0 + (idx & 15) * 4;
            float4 v = make_float4(0.f, 0.f, 0.f, 0.f);
            if (gk < Kreal)
                v = *reinterpret_cast<const float4*>(A + (size_t)(bm + row) * lda + gk);
            if (AOP == 1) {
                v.x = fmaxf(v.x + __ldg(cvec + gk + 0), 0.f);
                v.y = fmaxf(v.y + __ldg(cvec + gk + 1), 0.f);
                v.z = fmaxf(v.z + __ldg(cvec + gk + 2), 0.f);
                v.w = fmaxf(v.w + __ldg(cvec + gk + 3), 0.f);
            }
            aR[i] = v;
        }
    };
    // ---- A: regs -> split bf16, swizzled SMEM ----
    auto storeA = [&](const float4* aR, int buf) {
        char* hi = smem + aoff0 + (buf * 2 + 0) * ABYTES;
        char* lo = smem + aoff0 + (buf * 2 + 1) * ABYTES;
#pragma unroll
        for (int i = 0; i < 8; i++) {
            int idx = tid + i * 256;
            int row = idx >> 4;
            int f4  = idx & 15;
            float4 v = aR[i];
            unsigned short h0 = __bfloat16_as_ushort(__float2bfloat16_rn(v.x));
            unsigned short h1 = __bfloat16_as_ushort(__float2bfloat16_rn(v.y));
            unsigned short h2 = __bfloat16_as_ushort(__float2bfloat16_rn(v.z));
            unsigned short h3 = __bfloat16_as_ushort(__float2bfloat16_rn(v.w));
            unsigned short l0 = __bfloat16_as_ushort(__float2bfloat16_rn(v.x - __bfloat162float(__ushort_as_bfloat16(h0))));
            unsigned short l1 = __bfloat16_as_ushort(__float2bfloat16_rn(v.y - __bfloat162float(__ushort_as_bfloat16(h1))));
            unsigned short l2 = __bfloat16_as_ushort(__float2bfloat16_rn(v.z - __bfloat162float(__ushort_as_bfloat16(h2))));
            unsigned short l3 = __bfloat16_as_ushort(__float2bfloat16_rn(v.w - __bfloat162float(__ushort_as_bfloat16(h3))));
            uint2 hv = make_uint2((uint32_t)h0 | ((uint32_t)h1 << 16),
                                  (uint32_t)h2 | ((uint32_t)h3 << 16));
            uint2 lv = make_uint2((uint32_t)l0 | ((uint32_t)l1 << 16),
                                  (uint32_t)l2 | ((uint32_t)l3 << 16));
            uint32_t off = swz(row, f4 * 8);
            *reinterpret_cast<uint2*>(hi + off) = hv;
            *reinterpret_cast<uint2*>(lo + off) = lv;
        }
    };
    // ---- B: flat cp.async of pre-swizzled weights ----
    auto loadB_cp = [&](int chunk, int buf) {
        const char* sH = (const char*)Bhi + (size_t)chunk * Ntot * 128 + (size_t)bn * 128;
        const char* sL = (const char*)Blo + (size_t)chunk * Ntot * 128 + (size_t)bn * 128;
        uint32_t dH = sbase + boff0 + (buf * 2 + 0) * BBYTES;
        uint32_t dL = sbase + boff0 + (buf * 2 + 1) * BBYTES;
        for (int i = tid; i < BN * 8; i += 256) {
            CP_ASYNC16(dH + i * 16, sH + (size_t)i * 16);
            CP_ASYNC16(dL + i * 16, sL + (size_t)i * 16);
        }
    };
    // ---- compute one 64-k chunk out of SMEM buffer `buf` ----
    auto compute = [&](int buf) {
        uint32_t bAh = sbase + aoff0 + (buf * 2 + 0) * ABYTES;
        uint32_t bAl = sbase + aoff0 + (buf * 2 + 1) * ABYTES;
        uint32_t bBh = sbase + boff0 + (buf * 2 + 0) * BBYTES;
        uint32_t bBl = sbase + boff0 + (buf * 2 + 1) * BBYTES;
#pragma unroll
        for (int s = 0; s < 4; s++) {
            uint32_t Ah[MF][4], Al[MF][4], Bh[NF][2], Bl[NF][2];
            int ca = s * 32 + ((lane >> 4) << 4);
            int cb = s * 32 + (((lane >> 3) & 1) << 4);
#pragma unroll
            for (int mf = 0; mf < MF; mf++) {
                int row = wm * 64 + mf * 16 + (lane & 15);
                uint32_t off = (uint32_t)(row * 128 + (ca ^ ((row & 7) << 4)));
                ldsm_x4(Ah[mf], bAh + off);
                ldsm_x4(Al[mf], bAl + off);
            }
#pragma unroll
            for (int nf = 0; nf < NF; nf++) {
                int rn = wn * (NF * 8) + nf * 8 + (lane & 7);
                uint32_t off = (uint32_t)(rn * 128 + (cb ^ ((lane & 7) << 4)));
                ldsm_x2(Bh[nf], bBh + off);
                ldsm_x2(Bl[nf], bBl + off);
            }
#pragma unroll
            for (int mf = 0; mf < MF; mf++)
#pragma unroll
                for (int nf = 0; nf < NF; nf++) {
                    mma_bf16(acc[mf][nf], Ah[mf], Bh[nf]);
                    mma_bf16(acc[mf][nf], Ah[mf], Bl[nf]);
                    mma_bf16(acc[mf][nf], Al[mf], Bh[nf]);
                }
        }
    };

    // ---- pipeline ----
    float4 aR[8];
    loadA_g(0, aR);
    loadB_cp(0, 0);
    CP_COMMIT();
    storeA(aR, 0);
    CP_WAIT0();
    __syncthreads();

    for (int t = 0; t < nch; t++) {
        const int b = t & 1;
        if (t + 1 < nch) {
            loadA_g(t + 1, aR);
            loadB_cp(t + 1, b ^ 1);
            CP_COMMIT();
        }
        compute(b);
        if (t + 1 < nch) {
            storeA(aR, b ^ 1);
            CP_WAIT0();
            __syncthreads();
        }
    }

    // ---- epilogue ----
#pragma unroll
    for (int mf = 0; mf < MF; mf++) {
#pragma unroll
        for (int nf = 0; nf < NF; nf++) {
            int r0  = bm + wm * 64 + mf * 16 + (lane >> 2);
            int col = bn + wn * (NF * 8) + nf * 8 + (lane & 3) * 2;
            float2 v0 = make_float2(acc[mf][nf][0], acc[mf][nf][1]);
            float2 v1 = make_float2(acc[mf][nf][2], acc[mf][nf][3]);
            if (MODE == 0) {
                float bx = __ldg(bias + col), by = __ldg(bias + col + 1);
                v0.x += bx; v0.y += by;
                v1.x += bx; v1.y += by;
            } else if (MODE == 1) {
                float2 ra = *reinterpret_cast<const float2*>(res + (size_t)r0 * ldres + col);
                float2 rb = *reinterpret_cast<const float2*>(res + (size_t)(r0 + 8) * ldres + col);
                v0.x = fmaxf(v0.x + ra.x, 0.f); v0.y = fmaxf(v0.y + ra.y, 0.f);
                v1.x = fmaxf(v1.x + rb.x, 0.f); v1.y = fmaxf(v1.y + rb.y, 0.f);
            } else {
                float bx = __ldg(bias + col), by = __ldg(bias + col + 1);
                float2 ra = *reinterpret_cast<const float2*>(res + (size_t)r0 * ldres + col);
                float2 rb = *reinterpret_cast<const float2*>(res + (size_t)(r0 + 8) * ldres + col);
                v0.x += bx + ra.x; v0.y += by + ra.y;
                v1.x += bx + rb.x; v1.y += by + rb.y;
            }
            *reinterpret_cast<float2*>(C + (size_t)r0 * ldc + col) = v0;
            *reinterpret_cast<float2*>(C + (size_t)(r0 + 8) * ldc + col) = v1;
        }
    }
}

// ---------------- epilogue kernels ----------------
__global__ void rot6d_kernel(float* __restrict__ out)
{
    int idx = blockIdx.x * blockDim.x + threadIdx.x;
    if (idx >= NROWS * 24) return;
    int row = idx / 24;
    int j   = idx % 24;
    const float* p = g_theta + (size_t)row * THPAD + j * 6;
    float a1x = p[0], a2x = p[1];
    float a1y = p[2], a2y = p[3];
    float a1z = p[4], a2z = p[5];

    float n1 = fmaxf(sqrtf(a1x * a1x + a1y * a1y + a1z * a1z), 1e-12f);
    float b1x = a1x / n1, b1y = a1y / n1, b1z = a1z / n1;

    float d = b1x * a2x + b1y * a2y + b1z * a2z;
    float u2x = a2x - d * b1x, u2y = a2y - d * b1y, u2z = a2z - d * b1z;
    float n2 = fmaxf(sqrtf(u2x * u2x + u2y * u2y + u2z * u2z), 1e-12f);
    float b2x = u2x / n2, b2y = u2y / n2, b2z = u2z / n2;

    float b3x = b1y * b2z - b1z * b2y;
    float b3y = b1z * b2x - b1x * b2z;
    float b3z = b1x * b2y - b1y * b2x;

    float* o = out + (size_t)idx * 9;
    o[0] = b1x; o[1] = b2x; o[2] = b3x;
    o[3] = b1y; o[4] = b2y; o[5] = b3y;
    o[6] = b1z; o[7] = b2z; o[8] = b3z;
}

__global__ void copy_bc_kernel(float* __restrict__ out)
{
    int i = blockIdx.x * blockDim.x + threadIdx.x;
    if (i >= NROWS * 13) return;
    int row = i / 13;
    int k   = i % 13;
    float v = g_theta[(size_t)row * THPAD + NPOSE_ + k];
    size_t OB = (size_t)NROWS * 216;
    if (k < 10) out[OB + (size_t)row * 10 + k] = v;
    else        out[OB + (size_t)NROWS * 10 + (size_t)row * 3 + (k - 10)] = v;
}

// ---------------------------------------------------------------------------
extern "C" void kernel_launch(void* const* d_in, const int* in_sizes, int n_in,
                              void* d_out, int out_size)
{
    const float* x   = (const float*)d_in[0];
    // d_in[1] = pred_class (unused)
    const float* W1  = (const float*)d_in[2];
    const float* b1  = (const float*)d_in[3];
    const float* W2  = (const float*)d_in[4];
    const float* b2  = (const float*)d_in[5];
    const float* W3  = (const float*)d_in[6];
    const float* b3  = (const float*)d_in[7];
    const float* cr  = (const float*)d_in[8];
    const float* sh  = (const float*)d_in[9];
    const float* cam = (const float*)d_in[10];
    float* out = (float*)d_out;

    float *p_xw1, *p_h, *p_theta, *p_cvec, *p_bvec2, *p_tbias;
    cudaGetSymbolAddress((void**)&p_xw1,   g_xw1);
    cudaGetSymbolAddress((void**)&p_h,     g_h);
    cudaGetSymbolAddress((void**)&p_theta, g_theta);
    cudaGetSymbolAddress((void**)&p_cvec,  g_cvec);
    cudaGetSymbolAddress((void**)&p_bvec2, g_bvec2);
    cudaGetSymbolAddress((void**)&p_tbias, g_tbias);
    __nv_bfloat16 *w1a_h, *w1a_l, *w23_h, *w23_l, *w1t_h, *w1t_l;
    cudaGetSymbolAddress((void**)&w1a_h, g_w1a_hi);
    cudaGetSymbolAddress((void**)&w1a_l, g_w1a_lo);
    cudaGetSymbolAddress((void**)&w23_h, g_w23_hi);
    cudaGetSymbolAddress((void**)&w23_l, g_w23_lo);
    cudaGetSymbolAddress((void**)&w1t_h, g_w1t_hi);
    cudaGetSymbolAddress((void**)&w1t_l, g_w1t_lo);

    // dynamic smem: A 4*16KB + B 4*(BN*128)
    const size_t SM128 = 4 * 16384 + 4 * (128 * 128);   // 131072
    const size_t SM160 = 4 * 16384 + 4 * (160 * 128);   // 147456
    cudaFuncSetAttribute(mma_gemm<128, 0, 0>, cudaFuncAttributeMaxDynamicSharedMemorySize, SM128);
    cudaFuncSetAttribute(mma_gemm<160, 0, 1>, cudaFuncAttributeMaxDynamicSharedMemorySize, SM160);
    cudaFuncSetAttribute(mma_gemm<128, 1, 0>, cudaFuncAttributeMaxDynamicSharedMemorySize, SM128);
    cudaFuncSetAttribute(mma_gemm<160, 2, 0>, cudaFuncAttributeMaxDynamicSharedMemorySize, SM160);

    const int MB = NROWS / 128;   // 900

    prep_w23<<<CDIM, THPAD>>>(W2, W3);
    prep_vecs<<<1, CDIM>>>(W1, b2, W3, b3, cr, sh, cam);
    conv_w1a<<<(256 * 256 + 255) / 256, 256>>>(W1);
    conv_w23k<<<(256 * 160 + 255) / 256, 256>>>();
    conv_w1t<<<(192 * 256 + 255) / 256, 256>>>(W1);

    // GEMM1: xw1 = x @ W1[:256] + b1
    mma_gemm<128, 0, 0><<<dim3(2, MB), 256, SM128>>>(
        x, CDIM, CDIM, CDIM, w1a_h, w1a_l, 256, b1, nullptr, 0, nullptr, p_xw1, CDIM);

    // GEMM2 (iter 1 fused): theta = relu(xw1 + cvec) @ W23 + (theta0 + bvec2)
    mma_gemm<160, 0, 1><<<dim3(1, MB), 256, SM160>>>(
        p_xw1, CDIM, CDIM, CDIM, w23_h, w23_l, 160, p_tbias, nullptr, 0, p_cvec,
        p_theta, THPAD);

    for (int it = 0; it < 2; it++) {
        // h = relu(xw1 + theta @ W1t)   (K: 157 real, padded to 192; pad weights zero)
        mma_gemm<128, 1, 0><<<dim3(2, MB), 256, SM128>>>(
            p_theta, THPAD, THPAD, 192, w1t_h, w1t_l, 256, nullptr, p_xw1, CDIM,
            nullptr, p_h, CDIM);
        // theta += h @ W23 + bvec2
        mma_gemm<160, 2, 0><<<dim3(1, MB), 256, SM160>>>(
            p_h, CDIM, CDIM, CDIM, w23_h, w23_l, 160, p_bvec2, p_theta, THPAD,
            nullptr, p_theta, THPAD);
    }

    rot6d_kernel<<<(NROWS * 24 + 255) / 256, 256>>>(out);
    copy_bc_kernel<<<(NROWS * 13 + 255) / 256, 256>>>(out);
}

// round 7
// speedup vs baseline: 5.6899x; 1.0908x over previous
#include <cuda_runtime.h>
#include <cuda_bf16.h>
#include <math.h>
#include <stdint.h>

#define NROWS  115200           // 6*64*300
#define CDIM   256
#define THDIM  157
#define THPAD  160
#define N2PAD  192              // phase-2 N (W23 cols padded)
#define NPOSE_ 144

// ---------------- scratch (device globals; no allocation) ----------------
__device__ __align__(16) float g_xw1  [(size_t)NROWS * CDIM];
__device__ __align__(16) float g_theta[(size_t)NROWS * THPAD];
__device__ __align__(16) float g_w23f [CDIM * THPAD];
__device__ __align__(16) float g_cvec [CDIM];
__device__ __align__(16) float g_bvec2[N2PAD];
__device__ __align__(16) float g_tbias[N2PAD];

// Pre-split, pre-swizzled bf16 weights: [chunk64][n][128B row, XOR-swizzled]
__device__ __align__(16) __nv_bfloat16 g_w1a_hi[4 * 256 * 64], g_w1a_lo[4 * 256 * 64]; // N=256,K=256
__device__ __align__(16) __nv_bfloat16 g_w1t_hi[3 * 256 * 64], g_w1t_lo[3 * 256 * 64]; // N=256,K=192
__device__ __align__(16) __nv_bfloat16 g_w23_hi[4 * N2PAD * 64], g_w23_lo[4 * N2PAD * 64]; // N=192,K=256

// ---------------- helpers (baseline PTX, sm_80-class) ----------------
static __device__ __forceinline__ uint32_t smem_u32(const void* p) {
    uint32_t a;
    asm("{ .reg .u64 t; cvta.to.shared.u64 t, %1; cvt.u32.u64 %0, t; }"
        : "=r"(a) : "l"(p));
    return a;
}
static __device__ __forceinline__ void ldsm_x4(uint32_t* r, uint32_t a) {
    asm volatile("ldmatrix.sync.aligned.m8n8.x4.shared.b16 {%0,%1,%2,%3}, [%4];"
        : "=r"(r[0]), "=r"(r[1]), "=r"(r[2]), "=r"(r[3]) : "r"(a));
}
static __device__ __forceinline__ void ldsm_x2(uint32_t* r, uint32_t a) {
    asm volatile("ldmatrix.sync.aligned.m8n8.x2.shared.b16 {%0,%1}, [%2];"
        : "=r"(r[0]), "=r"(r[1]) : "r"(a));
}
static __device__ __forceinline__ void mma_bf16(float* d, const uint32_t* a,
                                                const uint32_t* b) {
    asm volatile(
        "mma.sync.aligned.m16n8k16.row.col.f32.bf16.bf16.f32 "
        "{%0,%1,%2,%3}, {%4,%5,%6,%7}, {%8,%9}, {%0,%1,%2,%3};"
        : "+f"(d[0]), "+f"(d[1]), "+f"(d[2]), "+f"(d[3])
        : "r"(a[0]), "r"(a[1]), "r"(a[2]), "r"(a[3]), "r"(b[0]), "r"(b[1]));
}
#define CP_ASYNC16(sa, gp) \
    asm volatile("cp.async.cg.shared.global [%0], [%1], 16;" :: "r"(sa), "l"(gp))
#define CP_COMMIT() asm volatile("cp.async.commit_group;" ::: "memory")
#define CP_WAIT0()  asm volatile("cp.async.wait_group 0;" ::: "memory")

__device__ __forceinline__ uint32_t swz(int row, int colbyte) {
    return (uint32_t)(row * 128 + (colbyte ^ ((row & 7) << 4)));
}
static __device__ __forceinline__ unsigned short bf_hi(float v) {
    return __bfloat16_as_ushort(__float2bfloat16_rn(v));
}
static __device__ __forceinline__ float bf_val(unsigned short u) {
    return __bfloat162float(__ushort_as_bfloat16(u));
}

// ---------------- weight / vector prep ----------------
__global__ void prep_w23(const float* __restrict__ W2, const float* __restrict__ W3)
{
    int k = blockIdx.x;          // 0..255
    int n = threadIdx.x;         // 0..159
    float acc = 0.f;
    if (n < THDIM)
        for (int j = 0; j < CDIM; j++)
            acc = fmaf(W2[k * CDIM + j], W3[j * THDIM + n], acc);
    g_w23f[k * THPAD + n] = (n < THDIM) ? acc : 0.f;
}

__global__ void prep_vecs(const float* __restrict__ W1, const float* __restrict__ b2,
                          const float* __restrict__ W3, const float* __restrict__ b3,
                          const float* __restrict__ cr, const float* __restrict__ sh,
                          const float* __restrict__ cam)
{
    __shared__ float th0[THDIM];
    int t = threadIdx.x;   // 0..255
    if (t < THDIM) {
        float v;
        if (t < NPOSE_)           v = cr[t];
        else if (t < NPOSE_ + 10) v = sh[t - NPOSE_];
        else                      v = cam[t - NPOSE_ - 10];
        th0[t] = v;
    }
    __syncthreads();
    {
        float acc = 0.f;
        for (int j = 0; j < THDIM; j++)
            acc = fmaf(th0[j], W1[(size_t)(CDIM + j) * CDIM + t], acc);
        g_cvec[t] = acc;
    }
    if (t < N2PAD) {
        float bv = 0.f;
        if (t < THDIM) {
            for (int j = 0; j < CDIM; j++)
                bv = fmaf(b2[j], W3[j * THDIM + t], bv);
            bv += b3[t];
        }
        g_bvec2[t] = bv;
        g_tbias[t] = bv + ((t < THDIM) ? th0[t] : 0.f);
    }
}

static __device__ __forceinline__ void put_w(__nv_bfloat16* hiArr, __nv_bfloat16* loArr,
                                             int Nrows, int k, int n, float v)
{
    unsigned short hb = bf_hi(v);
    unsigned short lb = bf_hi(v - bf_val(hb));
    int chunk = k >> 6, kc = k & 63;
    size_t byte = (size_t)chunk * ((size_t)Nrows * 128) + swz(n, kc * 2);
    *(unsigned short*)((char*)hiArr + byte) = hb;
    *(unsigned short*)((char*)loArr + byte) = lb;
}

__global__ void conv_w1a(const float* __restrict__ W1)
{
    int idx = blockIdx.x * blockDim.x + threadIdx.x;
    if (idx >= 256 * 256) return;
    int k = idx >> 8, n = idx & 255;
    put_w(g_w1a_hi, g_w1a_lo, 256, k, n, W1[(size_t)k * CDIM + n]);
}
__global__ void conv_w23k(void)
{
    int idx = blockIdx.x * blockDim.x + threadIdx.x;
    if (idx >= 256 * N2PAD) return;
    int k = idx / N2PAD, n = idx % N2PAD;
    float v = (n < THPAD) ? g_w23f[k * THPAD + n] : 0.f;
    put_w(g_w23_hi, g_w23_lo, N2PAD, k, n, v);
}
__global__ void conv_w1t(const float* __restrict__ W1)
{
    int idx = blockIdx.x * blockDim.x + threadIdx.x;
    if (idx >= 192 * 256) return;
    int k = idx >> 8, n = idx & 255;
    float v = (k < THDIM) ? W1[(size_t)(CDIM + k) * CDIM + n] : 0.f;
    put_w(g_w1t_hi, g_w1t_lo, 256, k, n, v);
}

// ---------------- fused double-GEMM kernel ----------------
// One 512-thread CTA owns a 128-row tile.
// Phase 1: V = A @ B1  (N=256, K = nch1*64), epilogue makes U (bf16 split in SMEM):
//   MODE 0: v = acc + b1[c]; xw1out = v (global); u = relu(v + cvec[c])
//   MODE 1: v = acc + xw1res (global); u = relu(v)       [h stays in SMEM]
// Phase 2: T = U @ W23  (N=192 padded, K=256), epilogue:
//   MODE 0: theta = acc2 + tbias[c]          (c < 160)
//   MODE 1: theta = acc2 + bvec2[c] + theta  (c < 160)
//
// SMEM (196608B dynamic):
//  R1 [0, 128K): ph1 B double-buffer (2 bufs x (hi+lo) x 32KB)
//               ph2 U split: split*64K + chunk*16K + swz(row, kc*2)
//  R2 [128K, 192K): ph1 A double-buffer (2 bufs x (hi+lo) x 16KB)
//                  ph2 B single buffer (hi at +0, lo at +24576)
template<int MODE>
__global__ void __launch_bounds__(512, 1)
fused2(const float* __restrict__ A, int lda, int Kreal, int nch1,
       const __nv_bfloat16* __restrict__ B1hi, const __nv_bfloat16* __restrict__ B1lo,
       const __nv_bfloat16* __restrict__ B2hi, const __nv_bfloat16* __restrict__ B2lo,
       const float* __restrict__ b1v, const float* __restrict__ cvec,
       const float* __restrict__ xw1, float* __restrict__ xw1out,
       const float* __restrict__ tbias, const float* __restrict__ bvec2,
       float* __restrict__ theta)
{
    constexpr int R2 = 131072;
    extern __shared__ char smem[];
    const uint32_t sbase = smem_u32(smem);
    const int tid  = threadIdx.x;
    const int lane = tid & 31;
    const int wid  = tid >> 5;        // 0..15
    const int wm   = wid & 1;         // 2 m-warps
    const int wn   = wid >> 1;        // 8 n-warps
    const int bm   = blockIdx.x * 128;

    // ================= PHASE 1 : N=256 =================
    float acc[4][4][4];
#pragma unroll
    for (int i = 0; i < 4; i++)
#pragma unroll
        for (int j = 0; j < 4; j++)
#pragma unroll
            for (int q = 0; q < 4; q++) acc[i][j][q] = 0.f;

    float4 aR[4];
    auto loadA_g = [&](int chunk) {
        int k0 = chunk << 6;
#pragma unroll
        for (int i = 0; i < 4; i++) {
            int idx = tid + i * 512;          // 0..2047
            int row = idx >> 4;
            int gk  = k0 + (idx & 15) * 4;
            float4 v = make_float4(0.f, 0.f, 0.f, 0.f);
            if (gk < Kreal)
                v = *reinterpret_cast<const float4*>(A + (size_t)(bm + row) * lda + gk);
            aR[i] = v;
        }
    };
    auto storeA = [&](int buf) {
        char* hi = smem + R2 + buf * 32768;
        char* lo = hi + 16384;
#pragma unroll
        for (int i = 0; i < 4; i++) {
            int idx = tid + i * 512;
            int row = idx >> 4;
            int f4  = idx & 15;
            float4 v = aR[i];
            unsigned short h0 = bf_hi(v.x), h1 = bf_hi(v.y), h2 = bf_hi(v.z), h3 = bf_hi(v.w);
            unsigned short l0 = bf_hi(v.x - bf_val(h0)), l1 = bf_hi(v.y - bf_val(h1));
            unsigned short l2 = bf_hi(v.z - bf_val(h2)), l3 = bf_hi(v.w - bf_val(h3));
            uint2 hv = make_uint2((uint32_t)h0 | ((uint32_t)h1 << 16),
                                  (uint32_t)h2 | ((uint32_t)h3 << 16));
            uint2 lv = make_uint2((uint32_t)l0 | ((uint32_t)l1 << 16),
                                  (uint32_t)l2 | ((uint32_t)l3 << 16));
            uint32_t off = swz(row, f4 * 8);
            *reinterpret_cast<uint2*>(hi + off) = hv;
            *reinterpret_cast<uint2*>(lo + off) = lv;
        }
    };
    auto loadB1 = [&](int chunk, int buf) {
        const char* sH = (const char*)B1hi + (size_t)chunk * (256 * 128);
        const char* sL = (const char*)B1lo + (size_t)chunk * (256 * 128);
        uint32_t dH = sbase + buf * 65536;
        uint32_t dL = dH + 32768;
#pragma unroll
        for (int i = 0; i < 4; i++) {
            int j = tid + i * 512;            // 0..2047 16B-vectors
            CP_ASYNC16(dH + j * 16, sH + (size_t)j * 16);
            CP_ASYNC16(dL + j * 16, sL + (size_t)j * 16);
        }
    };
    auto compute1 = [&](int buf) {
        uint32_t bAh = sbase + R2 + buf * 32768;
        uint32_t bAl = bAh + 16384;
        uint32_t bBh = sbase + buf * 65536;
        uint32_t bBl = bBh + 32768;
#pragma unroll
        for (int s = 0; s < 4; s++) {
            uint32_t Ah[4][4], Al[4][4], Bh[4][2], Bl[4][2];
            int ca = s * 32 + ((lane >> 4) << 4);
            int cb = s * 32 + (((lane >> 3) & 1) << 4);
#pragma unroll
            for (int mf = 0; mf < 4; mf++) {
                int row = wm * 64 + mf * 16 + (lane & 15);
                uint32_t off = (uint32_t)(row * 128 + (ca ^ ((row & 7) << 4)));
                ldsm_x4(Ah[mf], bAh + off);
                ldsm_x4(Al[mf], bAl + off);
            }
#pragma unroll
            for (int nf = 0; nf < 4; nf++) {
                int rn = wn * 32 + nf * 8 + (lane & 7);
                uint32_t off = (uint32_t)(rn * 128 + (cb ^ ((lane & 7) << 4)));
                ldsm_x2(Bh[nf], bBh + off);
                ldsm_x2(Bl[nf], bBl + off);
            }
#pragma unroll
            for (int mf = 0; mf < 4; mf++)
#pragma unroll
                for (int nf = 0; nf < 4; nf++) {
                    mma_bf16(acc[mf][nf], Ah[mf], Bh[nf]);
                    mma_bf16(acc[mf][nf], Ah[mf], Bl[nf]);
                    mma_bf16(acc[mf][nf], Al[mf], Bh[nf]);
                }
        }
    };

    loadA_g(0);
    loadB1(0, 0);
    CP_COMMIT();
    storeA(0);
    CP_WAIT0();
    __syncthreads();
    for (int t = 0; t < nch1; t++) {
        const int b = t & 1;
        if (t + 1 < nch1) {
            loadA_g(t + 1);
            loadB1(t + 1, b ^ 1);
            CP_COMMIT();
        }
        compute1(b);
        if (t + 1 < nch1) {
            storeA(b ^ 1);
            CP_WAIT0();
        }
        __syncthreads();            // last iter: protects R1/R2 reuse below
    }

    // ---- phase-1 epilogue: build U (bf16 split) in R1 ----
    auto store_u = [&](int row, int col, float ux, float uy) {
        unsigned short h0 = bf_hi(ux), h1 = bf_hi(uy);
        unsigned short l0 = bf_hi(ux - bf_val(h0)), l1 = bf_hi(uy - bf_val(h1));
        uint32_t off = (uint32_t)((col >> 6) * 16384) + swz(row, (col & 63) * 2);
        *reinterpret_cast<uint32_t*>(smem + off)         = (uint32_t)h0 | ((uint32_t)h1 << 16);
        *reinterpret_cast<uint32_t*>(smem + 65536 + off) = (uint32_t)l0 | ((uint32_t)l1 << 16);
    };
#pragma unroll
    for (int mf = 0; mf < 4; mf++) {
#pragma unroll
        for (int nf = 0; nf < 4; nf++) {
            int r0  = bm + wm * 64 + mf * 16 + (lane >> 2);
            int rl0 = wm * 64 + mf * 16 + (lane >> 2);
            int col = wn * 32 + nf * 8 + (lane & 3) * 2;
            float2 v0 = make_float2(acc[mf][nf][0], acc[mf][nf][1]);
            float2 v1 = make_float2(acc[mf][nf][2], acc[mf][nf][3]);
            if (MODE == 0) {
                float bx = __ldg(b1v + col), by = __ldg(b1v + col + 1);
                v0.x += bx; v0.y += by; v1.x += bx; v1.y += by;
                *reinterpret_cast<float2*>(xw1out + (size_t)r0 * CDIM + col) = v0;
                *reinterpret_cast<float2*>(xw1out + (size_t)(r0 + 8) * CDIM + col) = v1;
                float cx = __ldg(cvec + col), cy = __ldg(cvec + col + 1);
                store_u(rl0,     col, fmaxf(v0.x + cx, 0.f), fmaxf(v0.y + cy, 0.f));
                store_u(rl0 + 8, col, fmaxf(v1.x + cx, 0.f), fmaxf(v1.y + cy, 0.f));
            } else {
                float2 ra = *reinterpret_cast<const float2*>(xw1 + (size_t)r0 * CDIM + col);
                float2 rb = *reinterpret_cast<const float2*>(xw1 + (size_t)(r0 + 8) * CDIM + col);
                store_u(rl0,     col, fmaxf(v0.x + ra.x, 0.f), fmaxf(v0.y + ra.y, 0.f));
                store_u(rl0 + 8, col, fmaxf(v1.x + rb.x, 0.f), fmaxf(v1.y + rb.y, 0.f));
            }
        }
    }
    __syncthreads();

    // ================= PHASE 2 : N=192, K=256 =================
    float ac2[4][3][4];
#pragma unroll
    for (int i = 0; i < 4; i++)
#pragma unroll
        for (int j = 0; j < 3; j++)
#pragma unroll
            for (int q = 0; q < 4; q++) ac2[i][j][q] = 0.f;

    for (int c = 0; c < 4; c++) {
        {   // load W23 chunk c (single-buffered in R2)
            const char* sH = (const char*)B2hi + (size_t)c * (N2PAD * 128);
            const char* sL = (const char*)B2lo + (size_t)c * (N2PAD * 128);
            uint32_t dH = sbase + R2;
            uint32_t dL = dH + 24576;
#pragma unroll
            for (int i = 0; i < 3; i++) {
                int j = tid + i * 512;        // 0..1535 16B-vectors
                CP_ASYNC16(dH + j * 16, sH + (size_t)j * 16);
                CP_ASYNC16(dL + j * 16, sL + (size_t)j * 16);
            }
            CP_COMMIT();
            CP_WAIT0();
            __syncthreads();
        }
#pragma unroll
        for (int s = 0; s < 4; s++) {
            uint32_t Ah[4][4], Al[4][4], Bh[3][2], Bl[3][2];
            int ca = s * 32 + ((lane >> 4) << 4);
            int cb = s * 32 + (((lane >> 3) & 1) << 4);
            uint32_t uH = sbase + c * 16384;
            uint32_t uL = uH + 65536;
#pragma unroll
            for (int mf = 0; mf < 4; mf++) {
                int row = wm * 64 + mf * 16 + (lane & 15);
                uint32_t off = (uint32_t)(row * 128 + (ca ^ ((row & 7) << 4)));
                ldsm_x4(Ah[mf], uH + off);
                ldsm_x4(Al[mf], uL + off);
            }
#pragma unroll
            for (int nf = 0; nf < 3; nf++) {
                int rn = wn * 24 + nf * 8 + (lane & 7);
                uint32_t off = (uint32_t)(rn * 128 + (cb ^ ((lane & 7) << 4)));
                ldsm_x2(Bh[nf], sbase + R2 + off);
                ldsm_x2(Bl[nf], sbase + R2 + 24576 + off);
            }
#pragma unroll
            for (int mf = 0; mf < 4; mf++)
#pragma unroll
                for (int nf = 0; nf < 3; nf++) {
                    mma_bf16(ac2[mf][nf], Ah[mf], Bh[nf]);
                    mma_bf16(ac2[mf][nf], Ah[mf], Bl[nf]);
                    mma_bf16(ac2[mf][nf], Al[mf], Bh[nf]);
                }
        }
        __syncthreads();            // before next chunk overwrites R2
    }

    // ---- phase-2 epilogue ----
#pragma unroll
    for (int mf = 0; mf < 4; mf++) {
#pragma unroll
        for (int nf = 0; nf < 3; nf++) {
            int r0  = bm + wm * 64 + mf * 16 + (lane >> 2);
            int col = wn * 24 + nf * 8 + (lane & 3) * 2;
            if (col >= THPAD) continue;
            float2 v0 = make_float2(ac2[mf][nf][0], ac2[mf][nf][1]);
            float2 v1 = make_float2(ac2[mf][nf][2], ac2[mf][nf][3]);
            if (MODE == 0) {
                float bx = __ldg(tbias + col), by = __ldg(tbias + col + 1);
                v0.x += bx; v0.y += by; v1.x += bx; v1.y += by;
            } else {
                float bx = __ldg(bvec2 + col), by = __ldg(bvec2 + col + 1);
                float2 ra = *reinterpret_cast<const float2*>(theta + (size_t)r0 * THPAD + col);
                float2 rb = *reinterpret_cast<const float2*>(theta + (size_t)(r0 + 8) * THPAD + col);
                v0.x += bx + ra.x; v0.y += by + ra.y;
                v1.x += bx + rb.x; v1.y += by + rb.y;
            }
            *reinterpret_cast<float2*>(theta + (size_t)r0 * THPAD + col) = v0;
            *reinterpret_cast<float2*>(theta + (size_t)(r0 + 8) * THPAD + col) = v1;
        }
    }
}

// ---------------- output kernels ----------------
__global__ void rot6d_kernel(float* __restrict__ out)
{
    int idx = blockIdx.x * blockDim.x + threadIdx.x;
    if (idx >= NROWS * 24) return;
    int row = idx / 24;
    int j   = idx % 24;
    const float* p = g_theta + (size_t)row * THPAD + j * 6;
    float a1x = p[0], a2x = p[1];
    float a1y = p[2], a2y = p[3];
    float a1z = p[4], a2z = p[5];

    float n1 = fmaxf(sqrtf(a1x * a1x + a1y * a1y + a1z * a1z), 1e-12f);
    float b1x = a1x / n1, b1y = a1y / n1, b1z = a1z / n1;

    float d = b1x * a2x + b1y * a2y + b1z * a2z;
    float u2x = a2x - d * b1x, u2y = a2y - d * b1y, u2z = a2z - d * b1z;
    float n2 = fmaxf(sqrtf(u2x * u2x + u2y * u2y + u2z * u2z), 1e-12f);
    float b2x = u2x / n2, b2y = u2y / n2, b2z = u2z / n2;

    float b3x = b1y * b2z - b1z * b2y;
    float b3y = b1z * b2x - b1x * b2z;
    float b3z = b1x * b2y - b1y * b2x;

    float* o = out + (size_t)idx * 9;
    o[0] = b1x; o[1] = b2x; o[2] = b3x;
    o[3] = b1y; o[4] = b2y; o[5] = b3y;
    o[6] = b1z; o[7] = b2z; o[8] = b3z;
}

__global__ void copy_bc_kernel(float* __restrict__ out)
{
    int i = blockIdx.x * blockDim.x + threadIdx.x;
    if (i >= NROWS * 13) return;
    int row = i / 13;
    int k   = i % 13;
    float v = g_theta[(size_t)row * THPAD + NPOSE_ + k];
    size_t OB = (size_t)NROWS * 216;
    if (k < 10) out[OB + (size_t)row * 10 + k] = v;
    else        out[OB + (size_t)NROWS * 10 + (size_t)row * 3 + (k - 10)] = v;
}

// ---------------------------------------------------------------------------
extern "C" void kernel_launch(void* const* d_in, const int* in_sizes, int n_in,
                              void* d_out, int out_size)
{
    const float* x   = (const float*)d_in[0];
    // d_in[1] = pred_class (unused)
    const float* W1  = (const float*)d_in[2];
    const float* b1  = (const float*)d_in[3];
    const float* W2  = (const float*)d_in[4];
    const float* b2  = (const float*)d_in[5];
    const float* W3  = (const float*)d_in[6];
    const float* b3  = (const float*)d_in[7];
    const float* cr  = (const float*)d_in[8];
    const float* sh  = (const float*)d_in[9];
    const float* cam = (const float*)d_in[10];
    float* out = (float*)d_out;

    float *p_xw1, *p_theta, *p_cvec, *p_bvec2, *p_tbias;
    cudaGetSymbolAddress((void**)&p_xw1,   g_xw1);
    cudaGetSymbolAddress((void**)&p_theta, g_theta);
    cudaGetSymbolAddress((void**)&p_cvec,  g_cvec);
    cudaGetSymbolAddress((void**)&p_bvec2, g_bvec2);
    cudaGetSymbolAddress((void**)&p_tbias, g_tbias);
    __nv_bfloat16 *w1a_h, *w1a_l, *w23_h, *w23_l, *w1t_h, *w1t_l;
    cudaGetSymbolAddress((void**)&w1a_h, g_w1a_hi);
    cudaGetSymbolAddress((void**)&w1a_l, g_w1a_lo);
    cudaGetSymbolAddress((void**)&w23_h, g_w23_hi);
    cudaGetSymbolAddress((void**)&w23_l, g_w23_lo);
    cudaGetSymbolAddress((void**)&w1t_h, g_w1t_hi);
    cudaGetSymbolAddress((void**)&w1t_l, g_w1t_lo);

    const size_t SMEM = 196608;
    cudaFuncSetAttribute(fused2<0>, cudaFuncAttributeMaxDynamicSharedMemorySize, SMEM);
    cudaFuncSetAttribute(fused2<1>, cudaFuncAttributeMaxDynamicSharedMemorySize, SMEM);

    const int MB = NROWS / 128;   // 900

    prep_w23<<<CDIM, THPAD>>>(W2, W3);
    prep_vecs<<<1, CDIM>>>(W1, b2, W3, b3, cr, sh, cam);
    conv_w1a<<<(256 * 256 + 255) / 256, 256>>>(W1);
    conv_w23k<<<(256 * N2PAD + 255) / 256, 256>>>();
    conv_w1t<<<(192 * 256 + 255) / 256, 256>>>(W1);

    // K1: xw1 = x@W1a + b1 (written); theta = relu(xw1+cvec) @ W23 + tbias
    fused2<0><<<MB, 512, SMEM>>>(
        x, CDIM, CDIM, 4, w1a_h, w1a_l, w23_h, w23_l,
        b1, p_cvec, nullptr, p_xw1, p_tbias, nullptr, p_theta);

    // K2 (x2): h = relu(xw1 + theta@W1t) [SMEM only]; theta += h@W23 + bvec2
    for (int it = 0; it < 2; it++) {
        fused2<1><<<MB, 512, SMEM>>>(
            p_theta, THPAD, THPAD, 3, w1t_h, w1t_l, w23_h, w23_l,
            nullptr, nullptr, p_xw1, nullptr, nullptr, p_bvec2, p_theta);
    }

    rot6d_kernel<<<(NROWS * 24 + 255) / 256, 256>>>(out);
    copy_bc_kernel<<<(NROWS * 13 + 255) / 256, 256>>>(out);
}

// round 9
// speedup vs baseline: 6.1416x; 1.0794x over previous
#include <cuda_runtime.h>
#include <cuda_bf16.h>
#include <math.h>
#include <stdint.h>

#define NROWS  115200           // 6*64*300
#define CDIM   256
#define THDIM  157
#define THPAD  160
#define N2PAD  192
#define NPOSE_ 144
#define TILEM  64

// ---------------- scratch (device globals; no allocation) ----------------
__device__ __align__(16) float g_theta[(size_t)NROWS * THPAD];
__device__ __align__(16) float g_w23f [CDIM * THPAD];
__device__ __align__(16) float g_cvec [CDIM];
__device__ __align__(16) float g_bvec2[N2PAD];
__device__ __align__(16) float g_tbias[N2PAD];

// Pre-split, pre-swizzled bf16 weights: [chunk64][n][128B row, XOR-swizzled]
__device__ __align__(16) __nv_bfloat16 g_w1a_hi[4 * 256 * 64], g_w1a_lo[4 * 256 * 64]; // N=256,K=256
__device__ __align__(16) __nv_bfloat16 g_w1t_hi[3 * 256 * 64], g_w1t_lo[3 * 256 * 64]; // N=256,K=192
__device__ __align__(16) __nv_bfloat16 g_w23_hi[4 * N2PAD * 64], g_w23_lo[4 * N2PAD * 64]; // N=192,K=256

// ---------------- helpers (baseline PTX, sm_80-class) ----------------
static __device__ __forceinline__ uint32_t smem_u32(const void* p) {
    uint32_t a;
    asm("{ .reg .u64 t; cvta.to.shared.u64 t, %1; cvt.u32.u64 %0, t; }"
        : "=r"(a) : "l"(p));
    return a;
}
static __device__ __forceinline__ void ldsm_x4(uint32_t* r, uint32_t a) {
    asm volatile("ldmatrix.sync.aligned.m8n8.x4.shared.b16 {%0,%1,%2,%3}, [%4];"
        : "=r"(r[0]), "=r"(r[1]), "=r"(r[2]), "=r"(r[3]) : "r"(a));
}
static __device__ __forceinline__ void ldsm_x2(uint32_t* r, uint32_t a) {
    asm volatile("ldmatrix.sync.aligned.m8n8.x2.shared.b16 {%0,%1}, [%2];"
        : "=r"(r[0]), "=r"(r[1]) : "r"(a));
}
static __device__ __forceinline__ void mma_bf16(float* d, const uint32_t* a,
                                                const uint32_t* b) {
    asm volatile(
        "mma.sync.aligned.m16n8k16.row.col.f32.bf16.bf16.f32 "
        "{%0,%1,%2,%3}, {%4,%5,%6,%7}, {%8,%9}, {%0,%1,%2,%3};"
        : "+f"(d[0]), "+f"(d[1]), "+f"(d[2]), "+f"(d[3])
        : "r"(a[0]), "r"(a[1]), "r"(a[2]), "r"(a[3]), "r"(b[0]), "r"(b[1]));
}
#define CP_ASYNC16(sa, gp) \
    asm volatile("cp.async.cg.shared.global [%0], [%1], 16;" :: "r"(sa), "l"(gp))
#define CP_COMMIT() asm volatile("cp.async.commit_group;" ::: "memory")
#define CP_WAIT0()  asm volatile("cp.async.wait_group 0;" ::: "memory")
#define CP_WAIT1()  asm volatile("cp.async.wait_group 1;" ::: "memory")

__device__ __forceinline__ uint32_t swz(int row, int colbyte) {
    return (uint32_t)(row * 128 + (colbyte ^ ((row & 7) << 4)));
}
static __device__ __forceinline__ unsigned short bf_hi(float v) {
    return __bfloat16_as_ushort(__float2bfloat16_rn(v));
}
static __device__ __forceinline__ float bf_val(unsigned short u) {
    return __bfloat162float(__ushort_as_bfloat16(u));
}

// ---------------- weight / vector prep ----------------
__global__ void prep_w23(const float* __restrict__ W2, const float* __restrict__ W3)
{
    int k = blockIdx.x;          // 0..255
    int n = threadIdx.x;         // 0..159
    float acc = 0.f;
    if (n < THDIM)
        for (int j = 0; j < CDIM; j++)
            acc = fmaf(W2[k * CDIM + j], W3[j * THDIM + n], acc);
    g_w23f[k * THPAD + n] = (n < THDIM) ? acc : 0.f;
}

__global__ void prep_vecs(const float* __restrict__ W1, const float* __restrict__ b2,
                          const float* __restrict__ W3, const float* __restrict__ b3,
                          const float* __restrict__ cr, const float* __restrict__ sh,
                          const float* __restrict__ cam)
{
    __shared__ float th0[THDIM];
    int t = threadIdx.x;   // 0..255
    if (t < THDIM) {
        float v;
        if (t < NPOSE_)           v = cr[t];
        else if (t < NPOSE_ + 10) v = sh[t - NPOSE_];
        else                      v = cam[t - NPOSE_ - 10];
        th0[t] = v;
    }
    __syncthreads();
    {
        float acc = 0.f;
        for (int j = 0; j < THDIM; j++)
            acc = fmaf(th0[j], W1[(size_t)(CDIM + j) * CDIM + t], acc);
        g_cvec[t] = acc;
    }
    if (t < N2PAD) {
        float bv = 0.f;
        if (t < THDIM) {
            for (int j = 0; j < CDIM; j++)
                bv = fmaf(b2[j], W3[j * THDIM + t], bv);
            bv += b3[t];
        }
        g_bvec2[t] = bv;
        g_tbias[t] = bv + ((t < THDIM) ? th0[t] : 0.f);
    }
}

static __device__ __forceinline__ void put_w(__nv_bfloat16* hiArr, __nv_bfloat16* loArr,
                                             int Nrows, int k, int n, float v)
{
    unsigned short hb = bf_hi(v);
    unsigned short lb = bf_hi(v - bf_val(hb));
    int chunk = k >> 6, kc = k & 63;
    size_t byte = (size_t)chunk * ((size_t)Nrows * 128) + swz(n, kc * 2);
    *(unsigned short*)((char*)hiArr + byte) = hb;
    *(unsigned short*)((char*)loArr + byte) = lb;
}

__global__ void conv_w1a(const float* __restrict__ W1)
{
    int idx = blockIdx.x * blockDim.x + threadIdx.x;
    if (idx >= 256 * 256) return;
    int k = idx >> 8, n = idx & 255;
    put_w(g_w1a_hi, g_w1a_lo, 256, k, n, W1[(size_t)k * CDIM + n]);
}
__global__ void conv_w23k(void)
{
    int idx = blockIdx.x * blockDim.x + threadIdx.x;
    if (idx >= 256 * N2PAD) return;
    int k = idx / N2PAD, n = idx % N2PAD;
    float v = (n < THPAD) ? g_w23f[k * THPAD + n] : 0.f;
    put_w(g_w23_hi, g_w23_lo, N2PAD, k, n, v);
}
__global__ void conv_w1t(const float* __restrict__ W1)
{
    int idx = blockIdx.x * blockDim.x + threadIdx.x;
    if (idx >= 192 * 256) return;
    int k = idx >> 8, n = idx & 255;
    float v = (k < THDIM) ? W1[(size_t)(CDIM + k) * CDIM + n] : 0.f;
    put_w(g_w1t_hi, g_w1t_lo, 256, k, n, v);
}

// ---------------- MMA passes ----------------
// pass1: acc += Ah*Bh + Al*Bh  (B hi slot).  pass2: acc += Ah*Bl (B lo slot).
template<int NF>
__device__ __forceinline__ void pass1(uint32_t aHi, uint32_t aLo, uint32_t bHi,
                                      float (*acc)[4], int lane, int wm, int wn)
{
#pragma unroll
    for (int s = 0; s < 4; s++) {
        uint32_t Ah[4], Al[4], Bf[NF][2];
        int ca = s * 32 + ((lane >> 4) << 4);
        int cb = s * 32 + (((lane >> 3) & 1) << 4);
        int row = wm * 16 + (lane & 15);
        uint32_t aoff = (uint32_t)(row * 128 + (ca ^ ((row & 7) << 4)));
        ldsm_x4(Ah, aHi + aoff);
        ldsm_x4(Al, aLo + aoff);
#pragma unroll
        for (int nf = 0; nf < NF; nf++) {
            int rn = wn * (NF * 8) + nf * 8 + (lane & 7);
            uint32_t off = (uint32_t)(rn * 128 + (cb ^ ((lane & 7) << 4)));
            ldsm_x2(Bf[nf], bHi + off);
        }
#pragma unroll
        for (int nf = 0; nf < NF; nf++) mma_bf16(acc[nf], Ah, Bf[nf]);
#pragma unroll
        for (int nf = 0; nf < NF; nf++) mma_bf16(acc[nf], Al, Bf[nf]);
    }
}

template<int NF>
__device__ __forceinline__ void pass2(uint32_t aHi, uint32_t bLo,
                                      float (*acc)[4], int lane, int wm, int wn)
{
#pragma unroll
    for (int s = 0; s < 4; s++) {
        uint32_t Ah[4], Bf[NF][2];
        int ca = s * 32 + ((lane >> 4) << 4);
        int cb = s * 32 + (((lane >> 3) & 1) << 4);
        int row = wm * 16 + (lane & 15);
        uint32_t aoff = (uint32_t)(row * 128 + (ca ^ ((row & 7) << 4)));
        ldsm_x4(Ah, aHi + aoff);
#pragma unroll
        for (int nf = 0; nf < NF; nf++) {
            int rn = wn * (NF * 8) + nf * 8 + (lane & 7);
            uint32_t off = (uint32_t)(rn * 128 + (cb ^ ((lane & 7) << 4)));
            ldsm_x2(Bf[nf], bLo + off);
        }
#pragma unroll
        for (int nf = 0; nf < NF; nf++) mma_bf16(acc[nf], Ah, Bf[nf]);
    }
}

// GEMM phase with A already resident in SMEM (hi/lo chunk arrays, stride 8192).
// Bh/Bl two-slot rotated pipeline (loads always overlapped with compute).
template<int NF, int NCH>
__device__ __forceinline__ void gemm_static(
    const __nv_bfloat16* __restrict__ bhi, const __nv_bfloat16* __restrict__ blo,
    uint32_t aHiBase, uint32_t aLoBase,
    uint32_t S0, uint32_t S1, float (*acc)[4],
    int tid, int lane, int wm, int wn)
{
    constexpr int NV = NF * 256;          // 16B vectors per chunk per split
    auto cpy = [&](const __nv_bfloat16* src, int c, uint32_t dst) {
        const char* s = (const char*)src + (size_t)c * (NV * 16);
#pragma unroll
        for (int i = 0; i < NV / 512; i++) {
            int j = tid + i * 512;
            CP_ASYNC16(dst + j * 16, s + (size_t)j * 16);
        }
    };
    cpy(bhi, 0, S0); CP_COMMIT();
    CP_WAIT0(); __syncthreads();
#pragma unroll
    for (int c = 0; c < NCH; c++) {
        cpy(blo, c, S1); CP_COMMIT();
        uint32_t aHi = aHiBase + c * 8192, aLo = aLoBase + c * 8192;
        pass1<NF>(aHi, aLo, S0, acc, lane, wm, wn);
        __syncthreads();
        if (c + 1 < NCH) { cpy(bhi, c + 1, S0); CP_COMMIT(); CP_WAIT1(); }
        else             { CP_WAIT0(); }
        __syncthreads();
        pass2<NF>(aHi, S1, acc, lane, wm, wn);
        CP_WAIT0();
        __syncthreads();
    }
}

// ---------------- mega kernel: whole 3-iteration MLP for one 64-row tile ----------------
// SMEM (192KB): [0,64K) XW1 fp32 | [64K,128K) U/THS split (hi:64K+c*8K, lo:96K+c*8K;
//               K1 x-A dbuf overlays start) | [128K,192K) B slots S0,S1 (32K each)
__global__ void __launch_bounds__(512, 1)
mega_kernel(const float* __restrict__ x,
            const __nv_bfloat16* __restrict__ w1a_h, const __nv_bfloat16* __restrict__ w1a_l,
            const __nv_bfloat16* __restrict__ w1t_h, const __nv_bfloat16* __restrict__ w1t_l,
            const __nv_bfloat16* __restrict__ w23_h, const __nv_bfloat16* __restrict__ w23_l,
            const float* __restrict__ b1v, const float* __restrict__ cvec,
            const float* __restrict__ tbias, const float* __restrict__ bvec2,
            float* __restrict__ theta_g)
{
    extern __shared__ char smem[];
    const uint32_t sb = smem_u32(smem);
    const int tid = threadIdx.x, lane = tid & 31, wid = tid >> 5;
    const int wm = wid & 3, wn = wid >> 2;           // 4m x 4n warps
    const int bm = blockIdx.x * TILEM;

    const uint32_t S0  = sb + 131072, S1 = S0 + 32768;
    const uint32_t UHI = sb + 65536,  ULO = sb + 98304;
    const int er = wm * 16 + (lane >> 2);            // epilogue local row (and +8)

    // U/THS split store: (row, col)->(chunk col>>6, kc col&63)
    auto store_u = [&](int row, int col, float ux, float uy) {
        unsigned short h0 = bf_hi(ux), h1 = bf_hi(uy);
        unsigned short l0 = bf_hi(ux - bf_val(h0)), l1 = bf_hi(uy - bf_val(h1));
        uint32_t off = (uint32_t)((col >> 6) * 8192) + swz(row, (col & 63) * 2);
        *reinterpret_cast<uint32_t*>(smem + 65536 + off) = (uint32_t)h0 | ((uint32_t)h1 << 16);
        *reinterpret_cast<uint32_t*>(smem + 98304 + off) = (uint32_t)l0 | ((uint32_t)l1 << 16);
    };

    float th[6][4];                                   // theta carried fp32 in regs
#pragma unroll
    for (int i = 0; i < 6; i++)
#pragma unroll
        for (int q = 0; q < 4; q++) th[i][q] = 0.f;

    // ======== K1 phase 1: xw1 = x @ W1a + b1 (A streamed from global) ========
    {
        float acc[8][4];
#pragma unroll
        for (int i = 0; i < 8; i++)
#pragma unroll
            for (int q = 0; q < 4; q++) acc[i][q] = 0.f;

        float4 aR[2];
        auto loadAg = [&](int c) {
#pragma unroll
            for (int i = 0; i < 2; i++) {
                int idx = tid + i * 512;
                int row = idx >> 4, f4 = idx & 15;
                aR[i] = *reinterpret_cast<const float4*>(
                    x + (size_t)(bm + row) * CDIM + (c << 6) + f4 * 4);
            }
        };
        auto storeA = [&](int buf) {
            char* hi = smem + 65536 + buf * 16384;
            char* lo = hi + 8192;
#pragma unroll
            for (int i = 0; i < 2; i++) {
                int idx = tid + i * 512;
                int row = idx >> 4, f4 = idx & 15;
                float4 v = aR[i];
                unsigned short h0 = bf_hi(v.x), h1 = bf_hi(v.y), h2 = bf_hi(v.z), h3 = bf_hi(v.w);
                unsigned short l0 = bf_hi(v.x - bf_val(h0)), l1 = bf_hi(v.y - bf_val(h1));
                unsigned short l2 = bf_hi(v.z - bf_val(h2)), l3 = bf_hi(v.w - bf_val(h3));
                uint2 hv = make_uint2((uint32_t)h0 | ((uint32_t)h1 << 16),
                                      (uint32_t)h2 | ((uint32_t)h3 << 16));
                uint2 lv = make_uint2((uint32_t)l0 | ((uint32_t)l1 << 16),
                                      (uint32_t)l2 | ((uint32_t)l3 << 16));
                uint32_t off = swz(row, f4 * 8);
                *reinterpret_cast<uint2*>(hi + off) = hv;
                *reinterpret_cast<uint2*>(lo + off) = lv;
            }
        };
        auto cpyB = [&](const __nv_bfloat16* src, int c, uint32_t dst) {
            const char* s = (const char*)src + (size_t)c * 32768;
#pragma unroll
            for (int i = 0; i < 4; i++) {
                int j = tid + i * 512;
                CP_ASYNC16(dst + j * 16, s + (size_t)j * 16);
            }
        };

        cpyB(w1a_h, 0, S0); CP_COMMIT();
        loadAg(0); storeA(0);
        CP_WAIT0(); __syncthreads();
#pragma unroll
        for (int c = 0; c < 4; c++) {
            cpyB(w1a_l, c, S1); CP_COMMIT();
            if (c < 3) loadAg(c + 1);
            uint32_t aHi = sb + 65536 + (c & 1) * 16384, aLo = aHi + 8192;
            pass1<8>(aHi, aLo, S0, acc, lane, wm, wn);
            __syncthreads();
            if (c < 3) { cpyB(w1a_h, c + 1, S0); CP_COMMIT(); CP_WAIT1(); }
            else       { CP_WAIT0(); }
            __syncthreads();
            pass2<8>(aHi, S1, acc, lane, wm, wn);
            if (c < 3) storeA((c + 1) & 1);
            CP_WAIT0();
            __syncthreads();
        }

        // epilogue: XW1 (smem fp32) + U = relu(xw1 + cvec)
#pragma unroll
        for (int nf = 0; nf < 8; nf++) {
            int col = wn * 64 + nf * 8 + (lane & 3) * 2;
            float bx = __ldg(b1v + col), by = __ldg(b1v + col + 1);
            float2 v0 = make_float2(acc[nf][0] + bx, acc[nf][1] + by);
            float2 v1 = make_float2(acc[nf][2] + bx, acc[nf][3] + by);
            *reinterpret_cast<float2*>(smem + ((size_t)er * 256 + col) * 4) = v0;
            *reinterpret_cast<float2*>(smem + ((size_t)(er + 8) * 256 + col) * 4) = v1;
            float cx = __ldg(cvec + col), cy = __ldg(cvec + col + 1);
            store_u(er,     col, fmaxf(v0.x + cx, 0.f), fmaxf(v0.y + cy, 0.f));
            store_u(er + 8, col, fmaxf(v1.x + cx, 0.f), fmaxf(v1.y + cy, 0.f));
        }
        __syncthreads();
    }

    // ======== K1 phase 2: theta = U @ W23 + tbias ========
    {
        float ac2[6][4];
#pragma unroll
        for (int i = 0; i < 6; i++)
#pragma unroll
            for (int q = 0; q < 4; q++) ac2[i][q] = 0.f;
        gemm_static<6, 4>(w23_h, w23_l, UHI, ULO, S0, S1, ac2, tid, lane, wm, wn);
#pragma unroll
        for (int nf = 0; nf < 6; nf++) {
            int col = wn * 48 + nf * 8 + (lane & 3) * 2;
            float bx = __ldg(tbias + col), by = __ldg(tbias + col + 1);
            th[nf][0] = ac2[nf][0] + bx;  th[nf][1] = ac2[nf][1] + by;
            th[nf][2] = ac2[nf][2] + bx;  th[nf][3] = ac2[nf][3] + by;
            if (col < THPAD) {
                store_u(er,     col, th[nf][0], th[nf][1]);
                store_u(er + 8, col, th[nf][2], th[nf][3]);
            }
        }
        __syncthreads();
    }

    // ======== iterations 2, 3 ========
#pragma unroll 1
    for (int it = 0; it < 2; it++) {
        // phase 1: h = relu(xw1 + theta @ W1t); A = THS (in U region, chunks 0..2)
        {
            float acc[8][4];
#pragma unroll
            for (int i = 0; i < 8; i++)
#pragma unroll
                for (int q = 0; q < 4; q++) acc[i][q] = 0.f;
            gemm_static<8, 3>(w1t_h, w1t_l, UHI, ULO, S0, S1, acc, tid, lane, wm, wn);
#pragma unroll
            for (int nf = 0; nf < 8; nf++) {
                int col = wn * 64 + nf * 8 + (lane & 3) * 2;
                float2 r0 = *reinterpret_cast<const float2*>(smem + ((size_t)er * 256 + col) * 4);
                float2 r1 = *reinterpret_cast<const float2*>(smem + ((size_t)(er + 8) * 256 + col) * 4);
                store_u(er,     col, fmaxf(acc[nf][0] + r0.x, 0.f), fmaxf(acc[nf][1] + r0.y, 0.f));
                store_u(er + 8, col, fmaxf(acc[nf][2] + r1.x, 0.f), fmaxf(acc[nf][3] + r1.y, 0.f));
            }
            __syncthreads();
        }
        // phase 2: theta += h @ W23 + bvec2
        {
            float ac2[6][4];
#pragma unroll
            for (int i = 0; i < 6; i++)
#pragma unroll
                for (int q = 0; q < 4; q++) ac2[i][q] = 0.f;
            gemm_static<6, 4>(w23_h, w23_l, UHI, ULO, S0, S1, ac2, tid, lane, wm, wn);
#pragma unroll
            for (int nf = 0; nf < 6; nf++) {
                int col = wn * 48 + nf * 8 + (lane & 3) * 2;
                float bx = __ldg(bvec2 + col), by = __ldg(bvec2 + col + 1);
                th[nf][0] += ac2[nf][0] + bx;  th[nf][1] += ac2[nf][1] + by;
                th[nf][2] += ac2[nf][2] + bx;  th[nf][3] += ac2[nf][3] + by;
                if (col < THPAD) {
                    if (it == 0) {
                        store_u(er,     col, th[nf][0], th[nf][1]);
                        store_u(er + 8, col, th[nf][2], th[nf][3]);
                    } else {
                        *reinterpret_cast<float2*>(theta_g + (size_t)(bm + er) * THPAD + col) =
                            make_float2(th[nf][0], th[nf][1]);
                        *reinterpret_cast<float2*>(theta_g + (size_t)(bm + er + 8) * THPAD + col) =
                            make_float2(th[nf][2], th[nf][3]);
                    }
                }
            }
            __syncthreads();
        }
    }
}

// ---------------- output kernels ----------------
__global__ void rot6d_kernel(float* __restrict__ out)
{
    int idx = blockIdx.x * blockDim.x + threadIdx.x;
    if (idx >= NROWS * 24) return;
    int row = idx / 24;
    int j   = idx % 24;
    const float* p = g_theta + (size_t)row * THPAD + j * 6;
    float a1x = p[0], a2x = p[1];
    float a1y = p[2], a2y = p[3];
    float a1z = p[4], a2z = p[5];

    float n1 = fmaxf(sqrtf(a1x * a1x + a1y * a1y + a1z * a1z), 1e-12f);
    float b1x = a1x / n1, b1y = a1y / n1, b1z = a1z / n1;

    float d = b1x * a2x + b1y * a2y + b1z * a2z;
    float u2x = a2x - d * b1x, u2y = a2y - d * b1y, u2z = a2z - d * b1z;
    float n2 = fmaxf(sqrtf(u2x * u2x + u2y * u2y + u2z * u2z), 1e-12f);
    float b2x = u2x / n2, b2y = u2y / n2, b2z = u2z / n2;

    float b3x = b1y * b2z - b1z * b2y;
    float b3y = b1z * b2x - b1x * b2z;
    float b3z = b1x * b2y - b1y * b2x;

    float* o = out + (size_t)idx * 9;
    o[0] = b1x; o[1] = b2x; o[2] = b3x;
    o[3] = b1y; o[4] = b2y; o[5] = b3y;
    o[6] = b1z; o[7] = b2z; o[8] = b3z;
}

__global__ void copy_bc_kernel(float* __restrict__ out)
{
    int i = blockIdx.x * blockDim.x + threadIdx.x;
    if (i >= NROWS * 13) return;
    int row = i / 13;
    int k   = i % 13;
    float v = g_theta[(size_t)row * THPAD + NPOSE_ + k];
    size_t OB = (size_t)NROWS * 216;
    if (k < 10) out[OB + (size_t)row * 10 + k] = v;
    else        out[OB + (size_t)NROWS * 10 + (size_t)row * 3 + (k - 10)] = v;
}

// ---------------------------------------------------------------------------
extern "C" void kernel_launch(void* const* d_in, const int* in_sizes, int n_in,
                              void* d_out, int out_size)
{
    const float* x   = (const float*)d_in[0];
    // d_in[1] = pred_class (unused)
    const float* W1  = (const float*)d_in[2];
    const float* b1  = (const float*)d_in[3];
    const float* W2  = (const float*)d_in[4];
    const float* b2  = (const float*)d_in[5];
    const float* W3  = (const float*)d_in[6];
    const float* b3  = (const float*)d_in[7];
    const float* cr  = (const float*)d_in[8];
    const float* sh  = (const float*)d_in[9];
    const float* cam = (const float*)d_in[10];
    float* out = (float*)d_out;

    float *p_theta, *p_cvec, *p_bvec2, *p_tbias;
    cudaGetSymbolAddress((void**)&p_theta, g_theta);
    cudaGetSymbolAddress((void**)&p_cvec,  g_cvec);
    cudaGetSymbolAddress((void**)&p_bvec2, g_bvec2);
    cudaGetSymbolAddress((void**)&p_tbias, g_tbias);
    __nv_bfloat16 *w1a_h, *w1a_l, *w23_h, *w23_l, *w1t_h, *w1t_l;
    cudaGetSymbolAddress((void**)&w1a_h, g_w1a_hi);
    cudaGetSymbolAddress((void**)&w1a_l, g_w1a_lo);
    cudaGetSymbolAddress((void**)&w23_h, g_w23_hi);
    cudaGetSymbolAddress((void**)&w23_l, g_w23_lo);
    cudaGetSymbolAddress((void**)&w1t_h, g_w1t_hi);
    cudaGetSymbolAddress((void**)&w1t_l, g_w1t_lo);

    const size_t SMEM = 196608;     // 192KB
    cudaFuncSetAttribute(mega_kernel, cudaFuncAttributeMaxDynamicSharedMemorySize, SMEM);

    prep_w23<<<CDIM, THPAD>>>(W2, W3);
    prep_vecs<<<1, CDIM>>>(W1, b2, W3, b3, cr, sh, cam);
    conv_w1a<<<(256 * 256 + 255) / 256, 256>>>(W1);
    conv_w23k<<<(256 * N2PAD + 255) / 256, 256>>>();
    conv_w1t<<<(192 * 256 + 255) / 256, 256>>>(W1);

    mega_kernel<<<NROWS / TILEM, 512, SMEM>>>(
        x, w1a_h, w1a_l, w1t_h, w1t_l, w23_h, w23_l,
        b1, p_cvec, p_tbias, p_bvec2, p_theta);

    rot6d_kernel<<<(NROWS * 24 + 255) / 256, 256>>>(out);
    copy_bc_kernel<<<(NROWS * 13 + 255) / 256, 256>>>(out);
}

// round 10
// speedup vs baseline: 6.8112x; 1.1090x over previous
#include <cuda_runtime.h>
#include <cuda_bf16.h>
#include <math.h>
#include <stdint.h>

#define NROWS  115200           // 6*64*300
#define CDIM   256
#define THDIM  157
#define N2PAD  160              // W23 col pad AND theta K pad (= 4 warps * 5 frags * 8)
#define NPOSE_ 144
#define TILEM  64

// ---------------- scratch (device globals; no allocation) ----------------
__device__ __align__(16) float g_w23f [CDIM * N2PAD];
__device__ __align__(16) float g_cvec [CDIM];
__device__ __align__(16) float g_bvec2[N2PAD];
__device__ __align__(16) float g_tbias[N2PAD];

// Pre-split, pre-swizzled bf16 weights: [chunk64][n][128B row, XOR-swizzled]
__device__ __align__(16) __nv_bfloat16 g_w1a_hi[4 * 256 * 64], g_w1a_lo[4 * 256 * 64]; // N=256,K=256
__device__ __align__(16) __nv_bfloat16 g_w1t_hi[3 * 256 * 64], g_w1t_lo[3 * 256 * 64]; // N=256,K=160(zero-pad to 192)
__device__ __align__(16) __nv_bfloat16 g_w23_hi[4 * N2PAD * 64], g_w23_lo[4 * N2PAD * 64]; // N=160,K=256

// ---------------- helpers (baseline PTX, sm_80-class) ----------------
static __device__ __forceinline__ uint32_t smem_u32(const void* p) {
    uint32_t a;
    asm("{ .reg .u64 t; cvta.to.shared.u64 t, %1; cvt.u32.u64 %0, t; }"
        : "=r"(a) : "l"(p));
    return a;
}
static __device__ __forceinline__ void ldsm_x4(uint32_t* r, uint32_t a) {
    asm volatile("ldmatrix.sync.aligned.m8n8.x4.shared.b16 {%0,%1,%2,%3}, [%4];"
        : "=r"(r[0]), "=r"(r[1]), "=r"(r[2]), "=r"(r[3]) : "r"(a));
}
static __device__ __forceinline__ void ldsm_x2(uint32_t* r, uint32_t a) {
    asm volatile("ldmatrix.sync.aligned.m8n8.x2.shared.b16 {%0,%1}, [%2];"
        : "=r"(r[0]), "=r"(r[1]) : "r"(a));
}
static __device__ __forceinline__ void mma_bf16(float* d, const uint32_t* a,
                                                const uint32_t* b) {
    asm volatile(
        "mma.sync.aligned.m16n8k16.row.col.f32.bf16.bf16.f32 "
        "{%0,%1,%2,%3}, {%4,%5,%6,%7}, {%8,%9}, {%0,%1,%2,%3};"
        : "+f"(d[0]), "+f"(d[1]), "+f"(d[2]), "+f"(d[3])
        : "r"(a[0]), "r"(a[1]), "r"(a[2]), "r"(a[3]), "r"(b[0]), "r"(b[1]));
}
#define CP_ASYNC16(sa, gp) \
    asm volatile("cp.async.cg.shared.global [%0], [%1], 16;" :: "r"(sa), "l"(gp))
#define CP_COMMIT() asm volatile("cp.async.commit_group;" ::: "memory")
#define CP_WAIT0()  asm volatile("cp.async.wait_group 0;" ::: "memory")
#define CP_WAIT1()  asm volatile("cp.async.wait_group 1;" ::: "memory")

__device__ __forceinline__ uint32_t swz(int row, int colbyte) {
    return (uint32_t)(row * 128 + (colbyte ^ ((row & 7) << 4)));
}
static __device__ __forceinline__ unsigned short bf_hi(float v) {
    return __bfloat16_as_ushort(__float2bfloat16_rn(v));
}
static __device__ __forceinline__ float bf_val(unsigned short u) {
    return __bfloat162float(__ushort_as_bfloat16(u));
}

// ---------------- weight / vector prep ----------------
__global__ void prep_w23(const float* __restrict__ W2, const float* __restrict__ W3)
{
    int k = blockIdx.x;          // 0..255
    int n = threadIdx.x;         // 0..159
    float acc = 0.f;
    if (n < THDIM)
        for (int j = 0; j < CDIM; j++)
            acc = fmaf(W2[k * CDIM + j], W3[j * THDIM + n], acc);
    g_w23f[k * N2PAD + n] = (n < THDIM) ? acc : 0.f;
}

__global__ void prep_vecs(const float* __restrict__ W1, const float* __restrict__ b2,
                          const float* __restrict__ W3, const float* __restrict__ b3,
                          const float* __restrict__ cr, const float* __restrict__ sh,
                          const float* __restrict__ cam)
{
    __shared__ float th0[THDIM];
    int t = threadIdx.x;   // 0..255
    if (t < THDIM) {
        float v;
        if (t < NPOSE_)           v = cr[t];
        else if (t < NPOSE_ + 10) v = sh[t - NPOSE_];
        else                      v = cam[t - NPOSE_ - 10];
        th0[t] = v;
    }
    __syncthreads();
    {
        float acc = 0.f;
        for (int j = 0; j < THDIM; j++)
            acc = fmaf(th0[j], W1[(size_t)(CDIM + j) * CDIM + t], acc);
        g_cvec[t] = acc;
    }
    if (t < N2PAD) {
        float bv = 0.f;
        if (t < THDIM) {
            for (int j = 0; j < CDIM; j++)
                bv = fmaf(b2[j], W3[j * THDIM + t], bv);
            bv += b3[t];
        }
        g_bvec2[t] = bv;
        g_tbias[t] = bv + ((t < THDIM) ? th0[t] : 0.f);
    }
}

static __device__ __forceinline__ void put_w(__nv_bfloat16* hiArr, __nv_bfloat16* loArr,
                                             int Nrows, int k, int n, float v)
{
    unsigned short hb = bf_hi(v);
    unsigned short lb = bf_hi(v - bf_val(hb));
    int chunk = k >> 6, kc = k & 63;
    size_t byte = (size_t)chunk * ((size_t)Nrows * 128) + swz(n, kc * 2);
    *(unsigned short*)((char*)hiArr + byte) = hb;
    *(unsigned short*)((char*)loArr + byte) = lb;
}

__global__ void conv_w1a(const float* __restrict__ W1)
{
    int idx = blockIdx.x * blockDim.x + threadIdx.x;
    if (idx >= 256 * 256) return;
    int k = idx >> 8, n = idx & 255;
    put_w(g_w1a_hi, g_w1a_lo, 256, k, n, W1[(size_t)k * CDIM + n]);
}
__global__ void conv_w23k(void)
{
    int idx = blockIdx.x * blockDim.x + threadIdx.x;
    if (idx >= 256 * N2PAD) return;
    int k = idx / N2PAD, n = idx % N2PAD;
    put_w(g_w23_hi, g_w23_lo, N2PAD, k, n, g_w23f[k * N2PAD + n]);
}
__global__ void conv_w1t(const float* __restrict__ W1)
{
    int idx = blockIdx.x * blockDim.x + threadIdx.x;
    if (idx >= 192 * 256) return;               // zero-fill chunk 2 upper half too
    int k = idx >> 8, n = idx & 255;
    float v = (k < THDIM) ? W1[(size_t)(CDIM + k) * CDIM + n] : 0.f;
    put_w(g_w1t_hi, g_w1t_lo, 256, k, n, v);
}

// ---------------- MMA passes (SC = k16-steps in this chunk) ----------------
template<int NF, int SC>
__device__ __forceinline__ void pass1s(uint32_t aHi, uint32_t aLo, uint32_t bHi,
                                       float (*acc)[4], int lane, int wm, int wn)
{
#pragma unroll
    for (int s = 0; s < SC; s++) {
        uint32_t Ah[4], Al[4], Bf[NF][2];
        int ca = s * 32 + ((lane >> 4) << 4);
        int cb = s * 32 + (((lane >> 3) & 1) << 4);
        int row = wm * 16 + (lane & 15);
        uint32_t aoff = (uint32_t)(row * 128 + (ca ^ ((row & 7) << 4)));
        ldsm_x4(Ah, aHi + aoff);
        ldsm_x4(Al, aLo + aoff);
#pragma unroll
        for (int nf = 0; nf < NF; nf++) {
            int rn = wn * (NF * 8) + nf * 8 + (lane & 7);
            uint32_t off = (uint32_t)(rn * 128 + (cb ^ ((lane & 7) << 4)));
            ldsm_x2(Bf[nf], bHi + off);
        }
#pragma unroll
        for (int nf = 0; nf < NF; nf++) mma_bf16(acc[nf], Ah, Bf[nf]);
#pragma unroll
        for (int nf = 0; nf < NF; nf++) mma_bf16(acc[nf], Al, Bf[nf]);
    }
}

template<int NF, int SC>
__device__ __forceinline__ void pass2s(uint32_t aHi, uint32_t bLo,
                                       float (*acc)[4], int lane, int wm, int wn)
{
#pragma unroll
    for (int s = 0; s < SC; s++) {
        uint32_t Ah[4], Bf[NF][2];
        int ca = s * 32 + ((lane >> 4) << 4);
        int cb = s * 32 + (((lane >> 3) & 1) << 4);
        int row = wm * 16 + (lane & 15);
        uint32_t aoff = (uint32_t)(row * 128 + (ca ^ ((row & 7) << 4)));
        ldsm_x4(Ah, aHi + aoff);
#pragma unroll
        for (int nf = 0; nf < NF; nf++) {
            int rn = wn * (NF * 8) + nf * 8 + (lane & 7);
            uint32_t off = (uint32_t)(rn * 128 + (cb ^ ((lane & 7) << 4)));
            ldsm_x2(Bf[nf], bLo + off);
        }
#pragma unroll
        for (int nf = 0; nf < NF; nf++) mma_bf16(acc[nf], Ah, Bf[nf]);
    }
}

// Single-pass chunk for N=160 phases: 3 MMAs per (s, nf), both B splits resident.
template<int SC>
__device__ __forceinline__ void chunk160(uint32_t aHi, uint32_t aLo,
                                         uint32_t bH, uint32_t bL,
                                         float (*acc)[4], int lane, int wm, int wn)
{
#pragma unroll
    for (int s = 0; s < SC; s++) {
        uint32_t Ah[4], Al[4], Bh[5][2], Bl[5][2];
        int ca = s * 32 + ((lane >> 4) << 4);
        int cb = s * 32 + (((lane >> 3) & 1) << 4);
        int row = wm * 16 + (lane & 15);
        uint32_t aoff = (uint32_t)(row * 128 + (ca ^ ((row & 7) << 4)));
        ldsm_x4(Ah, aHi + aoff);
        ldsm_x4(Al, aLo + aoff);
#pragma unroll
        for (int nf = 0; nf < 5; nf++) {
            int rn = wn * 40 + nf * 8 + (lane & 7);
            uint32_t off = (uint32_t)(rn * 128 + (cb ^ ((lane & 7) << 4)));
            ldsm_x2(Bh[nf], bH + off);
            ldsm_x2(Bl[nf], bL + off);
        }
#pragma unroll
        for (int nf = 0; nf < 5; nf++) mma_bf16(acc[nf], Ah, Bh[nf]);
#pragma unroll
        for (int nf = 0; nf < 5; nf++) mma_bf16(acc[nf], Ah, Bl[nf]);
#pragma unroll
        for (int nf = 0; nf < 5; nf++) mma_bf16(acc[nf], Al, Bh[nf]);
    }
}

// ---------------- mega kernel ----------------
// One 512-thread CTA handles a 64-row tile end-to-end, including rot6d output.
// SMEM (212992B): [0,64K) XW1 fp32 (later: final theta fp32, stride 160)
//                 [64K,128K) U/THS bf16 split (hi 64K+c*8K, lo 96K+c*8K; K1 A-dbuf overlay)
//                 [128K,208K) B region: N=256 pass-split slots S0,S1 (32K each)
//                             N=160 single-pass slots buf*40K + split*20K
__global__ void __launch_bounds__(512, 1)
mega_kernel(const float* __restrict__ x,
            const __nv_bfloat16* __restrict__ w1a_h, const __nv_bfloat16* __restrict__ w1a_l,
            const __nv_bfloat16* __restrict__ w1t_h, const __nv_bfloat16* __restrict__ w1t_l,
            const __nv_bfloat16* __restrict__ w23_h, const __nv_bfloat16* __restrict__ w23_l,
            const float* __restrict__ b1v, const float* __restrict__ cvec,
            const float* __restrict__ tbias, const float* __restrict__ bvec2,
            float* __restrict__ out)
{
    extern __shared__ char smem[];
    const uint32_t sb = smem_u32(smem);
    const int tid = threadIdx.x, lane = tid & 31, wid = tid >> 5;
    const int wm = wid & 3, wn = wid >> 2;           // 4m x 4n warps
    const int bm = blockIdx.x * TILEM;

    const uint32_t BB  = sb + 131072;
    const uint32_t S0  = BB, S1 = BB + 32768;        // N=256 slots
    const uint32_t UHI = sb + 65536, ULO = sb + 98304;
    const int er = wm * 16 + (lane >> 2);

    auto store_u = [&](int row, int col, float ux, float uy) {
        unsigned short h0 = bf_hi(ux), h1 = bf_hi(uy);
        unsigned short l0 = bf_hi(ux - bf_val(h0)), l1 = bf_hi(uy - bf_val(h1));
        uint32_t off = (uint32_t)((col >> 6) * 8192) + swz(row, (col & 63) * 2);
        *reinterpret_cast<uint32_t*>(smem + 65536 + off) = (uint32_t)h0 | ((uint32_t)h1 << 16);
        *reinterpret_cast<uint32_t*>(smem + 98304 + off) = (uint32_t)l0 | ((uint32_t)l1 << 16);
    };
    // B copy helpers
    auto cpyB32 = [&](const __nv_bfloat16* src, int c, uint32_t dst) {
        const char* s = (const char*)src + (size_t)c * 32768;
#pragma unroll
        for (int i = 0; i < 4; i++) {
            int j = tid + i * 512;
            CP_ASYNC16(dst + j * 16, s + (size_t)j * 16);
        }
    };
    auto cpyB20 = [&](int c, int buf) {      // W23 chunk, both splits
        const char* sh = (const char*)w23_h + (size_t)c * 20480;
        const char* sl = (const char*)w23_l + (size_t)c * 20480;
        uint32_t dh = BB + buf * 40960, dl = dh + 20480;
#pragma unroll
        for (int i = 0; i < 3; i++) {
            int j = tid + i * 512;
            if (j < 1280) {
                CP_ASYNC16(dh + j * 16, sh + (size_t)j * 16);
                CP_ASYNC16(dl + j * 16, sl + (size_t)j * 16);
            }
        }
    };

    float th[5][4];
#pragma unroll
    for (int i = 0; i < 5; i++)
#pragma unroll
        for (int q = 0; q < 4; q++) th[i][q] = 0.f;

    // ======== K1 phase 1: xw1 = x @ W1a + b1 (A streamed from global) ========
    {
        float acc[8][4];
#pragma unroll
        for (int i = 0; i < 8; i++)
#pragma unroll
            for (int q = 0; q < 4; q++) acc[i][q] = 0.f;

        float4 aR[2];
        auto loadAg = [&](int c) {
#pragma unroll
            for (int i = 0; i < 2; i++) {
                int idx = tid + i * 512;
                int row = idx >> 4, f4 = idx & 15;
                aR[i] = *reinterpret_cast<const float4*>(
                    x + (size_t)(bm + row) * CDIM + (c << 6) + f4 * 4);
            }
        };
        auto storeA = [&](int buf) {
            char* hi = smem + 65536 + buf * 16384;
            char* lo = hi + 8192;
#pragma unroll
            for (int i = 0; i < 2; i++) {
                int idx = tid + i * 512;
                int row = idx >> 4, f4 = idx & 15;
                float4 v = aR[i];
                unsigned short h0 = bf_hi(v.x), h1 = bf_hi(v.y), h2 = bf_hi(v.z), h3 = bf_hi(v.w);
                unsigned short l0 = bf_hi(v.x - bf_val(h0)), l1 = bf_hi(v.y - bf_val(h1));
                unsigned short l2 = bf_hi(v.z - bf_val(h2)), l3 = bf_hi(v.w - bf_val(h3));
                uint2 hv = make_uint2((uint32_t)h0 | ((uint32_t)h1 << 16),
                                      (uint32_t)h2 | ((uint32_t)h3 << 16));
                uint2 lv = make_uint2((uint32_t)l0 | ((uint32_t)l1 << 16),
                                      (uint32_t)l2 | ((uint32_t)l3 << 16));
                uint32_t off = swz(row, f4 * 8);
                *reinterpret_cast<uint2*>(hi + off) = hv;
                *reinterpret_cast<uint2*>(lo + off) = lv;
            }
        };

        cpyB32(w1a_h, 0, S0); CP_COMMIT();
        loadAg(0); storeA(0);
        CP_WAIT0(); __syncthreads();
#pragma unroll
        for (int c = 0; c < 4; c++) {
            cpyB32(w1a_l, c, S1); CP_COMMIT();
            if (c < 3) loadAg(c + 1);
            uint32_t aHi = sb + 65536 + (c & 1) * 16384, aLo = aHi + 8192;
            pass1s<8, 4>(aHi, aLo, S0, acc, lane, wm, wn);
            __syncthreads();
            if (c < 3) { cpyB32(w1a_h, c + 1, S0); CP_COMMIT(); CP_WAIT1(); }
            else       { CP_WAIT0(); }
            __syncthreads();
            pass2s<8, 4>(aHi, S1, acc, lane, wm, wn);
            if (c < 3) storeA((c + 1) & 1);
            CP_WAIT0();
            __syncthreads();
        }
        // epilogue: XW1 fp32 (smem) + U = relu(xw1 + cvec)
#pragma unroll
        for (int nf = 0; nf < 8; nf++) {
            int col = wn * 64 + nf * 8 + (lane & 3) * 2;
            float bx = __ldg(b1v + col), by = __ldg(b1v + col + 1);
            float2 v0 = make_float2(acc[nf][0] + bx, acc[nf][1] + by);
            float2 v1 = make_float2(acc[nf][2] + bx, acc[nf][3] + by);
            *reinterpret_cast<float2*>(smem + ((size_t)er * 256 + col) * 4) = v0;
            *reinterpret_cast<float2*>(smem + ((size_t)(er + 8) * 256 + col) * 4) = v1;
            float cx = __ldg(cvec + col), cy = __ldg(cvec + col + 1);
            store_u(er,     col, fmaxf(v0.x + cx, 0.f), fmaxf(v0.y + cy, 0.f));
            store_u(er + 8, col, fmaxf(v1.x + cx, 0.f), fmaxf(v1.y + cy, 0.f));
        }
        __syncthreads();
    }

    // phase-2 runner: acc2 = U @ W23 (N=160, K=256, single-pass dbuf)
    auto run_p2 = [&](float (*ac2)[4]) {
        cpyB20(0, 0); CP_COMMIT();
        CP_WAIT0(); __syncthreads();
#pragma unroll
        for (int c = 0; c < 4; c++) {
            if (c < 3) { cpyB20(c + 1, (c + 1) & 1); CP_COMMIT(); }
            uint32_t bH = BB + (c & 1) * 40960, bL = bH + 20480;
            chunk160<4>(UHI + c * 8192, ULO + c * 8192, bH, bL, ac2, lane, wm, wn);
            CP_WAIT0();
            __syncthreads();
        }
    };

    // ======== K1 phase 2: theta = U @ W23 + tbias ========
    {
        float ac2[5][4];
#pragma unroll
        for (int i = 0; i < 5; i++)
#pragma unroll
            for (int q = 0; q < 4; q++) ac2[i][q] = 0.f;
        run_p2(ac2);
#pragma unroll
        for (int nf = 0; nf < 5; nf++) {
            int col = wn * 40 + nf * 8 + (lane & 3) * 2;
            float bx = __ldg(tbias + col), by = __ldg(tbias + col + 1);
            th[nf][0] = ac2[nf][0] + bx;  th[nf][1] = ac2[nf][1] + by;
            th[nf][2] = ac2[nf][2] + bx;  th[nf][3] = ac2[nf][3] + by;
            store_u(er,     col, th[nf][0], th[nf][1]);
            store_u(er + 8, col, th[nf][2], th[nf][3]);
        }
        __syncthreads();
    }

    // ======== iterations 2, 3 ========
#pragma unroll 1
    for (int it = 0; it < 2; it++) {
        // phase 1: h = relu(xw1 + theta @ W1t); A = THS chunks {4,4,2} k16-steps
        {
            float acc[8][4];
#pragma unroll
            for (int i = 0; i < 8; i++)
#pragma unroll
                for (int q = 0; q < 4; q++) acc[i][q] = 0.f;

            cpyB32(w1t_h, 0, S0); CP_COMMIT();
            CP_WAIT0(); __syncthreads();
#pragma unroll
            for (int c = 0; c < 3; c++) {
                cpyB32(w1t_l, c, S1); CP_COMMIT();
                uint32_t aHi = UHI + c * 8192, aLo = ULO + c * 8192;
                if (c < 2) pass1s<8, 4>(aHi, aLo, S0, acc, lane, wm, wn);
                else       pass1s<8, 2>(aHi, aLo, S0, acc, lane, wm, wn);
                __syncthreads();
                if (c < 2) { cpyB32(w1t_h, c + 1, S0); CP_COMMIT(); CP_WAIT1(); }
                else       { CP_WAIT0(); }
                __syncthreads();
                if (c < 2) pass2s<8, 4>(aHi, S1, acc, lane, wm, wn);
                else       pass2s<8, 2>(aHi, S1, acc, lane, wm, wn);
                CP_WAIT0();
                __syncthreads();
            }
#pragma unroll
            for (int nf = 0; nf < 8; nf++) {
                int col = wn * 64 + nf * 8 + (lane & 3) * 2;
                float2 r0 = *reinterpret_cast<const float2*>(smem + ((size_t)er * 256 + col) * 4);
                float2 r1 = *reinterpret_cast<const float2*>(smem + ((size_t)(er + 8) * 256 + col) * 4);
                store_u(er,     col, fmaxf(acc[nf][0] + r0.x, 0.f), fmaxf(acc[nf][1] + r0.y, 0.f));
                store_u(er + 8, col, fmaxf(acc[nf][2] + r1.x, 0.f), fmaxf(acc[nf][3] + r1.y, 0.f));
            }
            __syncthreads();
        }
        // phase 2: theta += h @ W23 + bvec2
        {
            float ac2[5][4];
#pragma unroll
            for (int i = 0; i < 5; i++)
#pragma unroll
                for (int q = 0; q < 4; q++) ac2[i][q] = 0.f;
            run_p2(ac2);
#pragma unroll
            for (int nf = 0; nf < 5; nf++) {
                int col = wn * 40 + nf * 8 + (lane & 3) * 2;
                float bx = __ldg(bvec2 + col), by = __ldg(bvec2 + col + 1);
                th[nf][0] += ac2[nf][0] + bx;  th[nf][1] += ac2[nf][1] + by;
                th[nf][2] += ac2[nf][2] + bx;  th[nf][3] += ac2[nf][3] + by;
                if (it == 0) {
                    store_u(er,     col, th[nf][0], th[nf][1]);
                    store_u(er + 8, col, th[nf][2], th[nf][3]);
                } else {
                    // final theta fp32 into (dead) XW1 region, stride 160
                    *reinterpret_cast<float2*>(smem + ((size_t)er * 160 + col) * 4) =
                        make_float2(th[nf][0], th[nf][1]);
                    *reinterpret_cast<float2*>(smem + ((size_t)(er + 8) * 160 + col) * 4) =
                        make_float2(th[nf][2], th[nf][3]);
                }
            }
            __syncthreads();
        }
    }

    // ======== fused output epilogue: rot6d + betas/cam ========
    const float* ths = reinterpret_cast<const float*>(smem);
#pragma unroll
    for (int k2 = 0; k2 < 3; k2++) {
        int idx = tid + k2 * 512;            // 0..1535 = 64 rows * 24 joints
        int row = idx / 24, j = idx % 24;
        const float* p = ths + row * 160 + j * 6;
        float a1x = p[0], a2x = p[1];
        float a1y = p[2], a2y = p[3];
        float a1z = p[4], a2z = p[5];

        float n1 = fmaxf(sqrtf(a1x * a1x + a1y * a1y + a1z * a1z), 1e-12f);
        float b1x = a1x / n1, b1y = a1y / n1, b1z = a1z / n1;

        float d = b1x * a2x + b1y * a2y + b1z * a2z;
        float u2x = a2x - d * b1x, u2y = a2y - d * b1y, u2z = a2z - d * b1z;
        float n2 = fmaxf(sqrtf(u2x * u2x + u2y * u2y + u2z * u2z), 1e-12f);
        float b2x = u2x / n2, b2y = u2y / n2, b2z = u2z / n2;

        float b3x = b1y * b2z - b1z * b2y;
        float b3y = b1z * b2x - b1x * b2z;
        float b3z = b1x * b2y - b1y * b2x;

        float* o = out + ((size_t)(bm + row) * 24 + j) * 9;
        o[0] = b1x; o[1] = b2x; o[2] = b3x;
        o[3] = b1y; o[4] = b2y; o[5] = b3y;
        o[6] = b1z; o[7] = b2z; o[8] = b3z;
    }
    {
        const size_t OB  = (size_t)NROWS * 216;
        const size_t OB2 = OB + (size_t)NROWS * 10;
        for (int i = tid; i < TILEM * 13; i += 512) {
            int row = i / 13, k = i % 13;
            float v = ths[row * 160 + NPOSE_ + k];
            if (k < 10) out[OB + (size_t)(bm + row) * 10 + k] = v;
            else        out[OB2 + (size_t)(bm + row) * 3 + (k - 10)] = v;
        }
    }
}

// ---------------------------------------------------------------------------
extern "C" void kernel_launch(void* const* d_in, const int* in_sizes, int n_in,
                              void* d_out, int out_size)
{
    const float* x   = (const float*)d_in[0];
    // d_in[1] = pred_class (unused)
    const float* W1  = (const float*)d_in[2];
    const float* b1  = (const float*)d_in[3];
    const float* W2  = (const float*)d_in[4];
    const float* b2  = (const float*)d_in[5];
    const float* W3  = (const float*)d_in[6];
    const float* b3  = (const float*)d_in[7];
    const float* cr  = (const float*)d_in[8];
    const float* sh  = (const float*)d_in[9];
    const float* cam = (const float*)d_in[10];
    float* out = (float*)d_out;

    float *p_cvec, *p_bvec2, *p_tbias;
    cudaGetSymbolAddress((void**)&p_cvec,  g_cvec);
    cudaGetSymbolAddress((void**)&p_bvec2, g_bvec2);
    cudaGetSymbolAddress((void**)&p_tbias, g_tbias);
    __nv_bfloat16 *w1a_h, *w1a_l, *w23_h, *w23_l, *w1t_h, *w1t_l;
    cudaGetSymbolAddress((void**)&w1a_h, g_w1a_hi);
    cudaGetSymbolAddress((void**)&w1a_l, g_w1a_lo);
    cudaGetSymbolAddress((void**)&w23_h, g_w23_hi);
    cudaGetSymbolAddress((void**)&w23_l, g_w23_lo);
    cudaGetSymbolAddress((void**)&w1t_h, g_w1t_hi);
    cudaGetSymbolAddress((void**)&w1t_l, g_w1t_lo);

    const size_t SMEM = 212992;     // 208KB
    cudaFuncSetAttribute(mega_kernel, cudaFuncAttributeMaxDynamicSharedMemorySize, SMEM);

    prep_w23<<<CDIM, N2PAD>>>(W2, W3);
    prep_vecs<<<1, CDIM>>>(W1, b2, W3, b3, cr, sh, cam);
    conv_w1a<<<(256 * 256 + 255) / 256, 256>>>(W1);
    conv_w23k<<<(256 * N2PAD + 255) / 256, 256>>>();
    conv_w1t<<<(192 * 256 + 255) / 256, 256>>>(W1);

    mega_kernel<<<NROWS / TILEM, 512, SMEM>>>(
        x, w1a_h, w1a_l, w1t_h, w1t_l, w23_h, w23_l,
        b1, p_cvec, p_tbias, p_bvec2, out);
}